// round 5
// baseline (speedup 1.0000x reference)
#include <cuda_runtime.h>
#include <cuda_bf16.h>

#define SEQ   512
#define T_LEN 65536
#define NN    131072
#define NHALF 65536
#define N2    2048

// Scratch (device globals; no allocations allowed)
__device__ float2 g_z[(size_t)SEQ * NN];   // 512 MiB workspace
__device__ float2 g_tw[NN];                // g_tw[h+p] = exp(-i*pi*p/h)

static __device__ __forceinline__ float2 cmul(float2 a, float2 b) {
    return make_float2(fmaf(a.x, b.x, -a.y * b.y), fmaf(a.x, b.y, a.y * b.x));
}
static __device__ __forceinline__ float2 cadd(float2 a, float2 b) { return make_float2(a.x+b.x, a.y+b.y); }
static __device__ __forceinline__ float2 csub(float2 a, float2 b) { return make_float2(a.x-b.x, a.y-b.y); }
static __device__ __forceinline__ float2 mulnI(float2 a) { return make_float2(a.y, -a.x); }   // * (-i)
static __device__ __forceinline__ float2 mulpI(float2 a) { return make_float2(-a.y, a.x); }   // * (+i)
static __device__ __forceinline__ float2 cconj(float2 a) { return make_float2(a.x, -a.y); }

// W_{2*Mhalf}^q  for q in [0, 2*Mhalf)   (direct table lookup, read-only path)
static __device__ __forceinline__ float2 twid(int Mhalf, int q) {
    if (q < Mhalf) return __ldg(&g_tw[Mhalf + q]);
    float2 t = __ldg(&g_tw[q]);            // == g_tw[Mhalf + (q - Mhalf)]
    return make_float2(-t.x, -t.y);
}
// conj(W_{2*Mhalf}^q)
static __device__ __forceinline__ float2 twidc(int Mhalf, int q) {
    if (q < Mhalf) { float2 t = __ldg(&g_tw[Mhalf + q]); return make_float2(t.x, -t.y); }
    float2 t = __ldg(&g_tw[q]);
    return make_float2(-t.x, t.y);
}

// 8-pt DFT, natural in/out. INV => conjugated twiddles (unnormalized inverse).
template<bool INV>
static __device__ __forceinline__ void fft8(float2 z[8]) {
    const float C = 0.70710678118654752440f;
    float2 t0=cadd(z[0],z[4]), t1=cadd(z[1],z[5]), t2=cadd(z[2],z[6]), t3=cadd(z[3],z[7]);
    float2 s0=csub(z[0],z[4]), s1=csub(z[1],z[5]), s2=csub(z[2],z[6]), s3=csub(z[3],z[7]);
    if (!INV) {
        s1 = cmul(s1, make_float2(C,-C)); s2 = mulnI(s2); s3 = cmul(s3, make_float2(-C,-C));
    } else {
        s1 = cmul(s1, make_float2(C, C)); s2 = mulpI(s2); s3 = cmul(s3, make_float2(-C, C));
    }
    float2 a0=cadd(t0,t2), a1=csub(t0,t2), a2=cadd(t1,t3), a3=csub(t1,t3);
    a3 = INV ? mulpI(a3) : mulnI(a3);
    float2 b0=cadd(s0,s2), b1=csub(s0,s2), b2=cadd(s1,s3), b3=csub(s1,s3);
    b3 = INV ? mulpI(b3) : mulnI(b3);
    z[0]=cadd(a0,a2); z[4]=csub(a0,a2);
    z[2]=cadd(a1,a3); z[6]=csub(a1,a3);
    z[1]=cadd(b0,b2); z[5]=csub(b0,b2);
    z[3]=cadd(b1,b3); z[7]=csub(b1,b3);
}

template<bool INV>
static __device__ __forceinline__ void fft4(float2 z[4]) {
    float2 a0=cadd(z[0],z[2]), a1=csub(z[0],z[2]);
    float2 a2=cadd(z[1],z[3]), a3=csub(z[1],z[3]);
    a3 = INV ? mulpI(a3) : mulnI(a3);
    z[0]=cadd(a0,a2); z[2]=csub(a0,a2);
    z[1]=cadd(a1,a3); z[3]=csub(a1,a3);
}

// Hermitian unpack + pointwise: Za = Z[k], Zb = Z[N-k]; returns Y[k] = X[k]*H[k]
static __device__ __forceinline__ float2 pw(float2 Za, float2 Zb) {
    float2 X = make_float2(0.5f*(Za.x+Zb.x),  0.5f*(Za.y-Zb.y));
    float2 H = make_float2(0.5f*(Za.y+Zb.y), -0.5f*(Za.x-Zb.x));
    return cmul(X, H);
}

#define PAD(p) ((p) + (((p) >> 5) << 2))
#define POS(k2) ((((k2)&7)<<8) + ((((k2)>>3)&7)<<5) + ((((k2)>>6)&7)<<2) + ((k2)>>9))

__global__ void k_init_tw() {
    int idx = blockIdx.x * blockDim.x + threadIdx.x;
    if (idx >= NN) return;
    if (idx == 0) { g_tw[0] = make_float2(1.0f, 0.0f); return; }
    int h = 1 << (31 - __clz(idx));
    int p = idx - h;
    float s, c;
    sincospif(-(float)p / (float)h, &s, &c);
    g_tw[idx] = make_float2(c, s);
}

// ---------------------------------------------------------------------------
// Stage 1: pack z = bf16(x) + i*h (rows n1>=32 are zero) + 64-pt FFT along n1
// (two register radix-8 passes, one smem exchange) + twiddle W_N^{k1*n2}.
// Output: g_z[s][k1*2048 + n2]
// ---------------------------------------------------------------------------
__global__ void __launch_bounds__(256) k_stage1(const float* __restrict__ x,
                                                const float* __restrict__ hk) {
    __shared__ float2 sm[64 * 32];
    const int s   = blockIdx.y;
    const int col = threadIdx.x & 31;
    const int a   = threadIdx.x >> 5;          // 0..7
    const int n2  = blockIdx.x * 32 + col;
    const float* xs = x  + (size_t)s * T_LEN;
    const float* hs = hk + (size_t)s * T_LEN;

    float2 v[8];
    #pragma unroll
    for (int b = 0; b < 4; b++) {
        int n = (a + 8*b) * N2 + n2;           // < 65536 always
        v[b] = make_float2(__bfloat162float(__float2bfloat16_rn(xs[n])), hs[n]);
    }
    // fft8 over b with upper half zero (t = z, s = z)
    {
        const float C = 0.70710678118654752440f;
        float2 t0=v[0], t1=v[1], t2=v[2], t3=v[3];
        float2 s0=v[0];
        float2 s1=cmul(v[1], make_float2(C,-C));
        float2 s2=mulnI(v[2]);
        float2 s3=cmul(v[3], make_float2(-C,-C));
        float2 a0=cadd(t0,t2), a1=csub(t0,t2), a2=cadd(t1,t3), a3=mulnI(csub(t1,t3));
        float2 b0=cadd(s0,s2), b1=csub(s0,s2), b2=cadd(s1,s3), b3=mulnI(csub(s1,s3));
        v[0]=cadd(a0,a2); v[4]=csub(a0,a2);
        v[2]=cadd(a1,a3); v[6]=csub(a1,a3);
        v[1]=cadd(b0,b2); v[5]=csub(b0,b2);
        v[3]=cadd(b1,b3); v[7]=csub(b1,b3);
    }
    // twiddle W_64^{a*j}  (a*j <= 49 < 64)
    #pragma unroll
    for (int j = 1; j < 8; j++) v[j] = cmul(v[j], twid(32, a*j));
    #pragma unroll
    for (int j = 0; j < 8; j++) sm[(j*8 + a)*32 + col] = v[j];
    __syncthreads();

    const int j = a;                            // phase-2 role
    #pragma unroll
    for (int q = 0; q < 8; q++) v[q] = sm[(j*8 + q)*32 + col];
    fft8<false>(v);                             // over a -> m ; k1 = j + 8m

    float2* zs = g_z + (size_t)s * NN;
    {
        int q = n2 * j;                         // exponent of W_N; stays < 2*NHALF
        const int step = 8 * n2;
        #pragma unroll
        for (int m = 0; m < 8; m++) {
            int k1 = j + 8*m;
            zs[k1 * N2 + n2] = cmul(v[m], twid(NHALF, q));
            q += step;
        }
    }
}

// ---------------------------------------------------------------------------
// Stage 2: per paired rows {g, 64-g} ({0,32} for g==0):
//   fwd FFT-2048 both rows (radix 8,8,8,4; digit-reversed positions)
//   -> Hermitian pointwise (complement p <-> 2047-p is position-local)
//   -> inverse FFT-2048 for row A ONLY (output realness implies
//      u[64-k1] = conj(u[k1]) after the conj inter-twiddle, so rows > 32
//      are never materialized) -> store rows 0..32 only.
// ---------------------------------------------------------------------------
__global__ void __launch_bounds__(512) k_stage2() {
    __shared__ float2 smAB[2 * 2304];
    const int s = blockIdx.y;
    const int g = blockIdx.x;                   // 0..31
    const int rowA = g;
    const int rowB = (g == 0) ? 32 : 64 - g;
    const int tid = threadIdx.x;
    const int r = tid >> 8;                     // which row this thread serves
    const int u = tid & 255;
    const int myrow = r ? rowB : rowA;
    const bool invB = (g == 0);                 // does row B need the inverse path?
    float2* zs   = g_z + (size_t)s * NN;
    float2* glob = zs + myrow * N2;
    float2* sm   = smAB + r * 2304;
    float2* smA  = smAB;
    float2* smB  = smAB + 2304;

    float2 v[8];
    // S1: radix-8 over b (stride 256), twiddle W_2048^{u*j} (u*j <= 1785 < 2048)
    #pragma unroll
    for (int b = 0; b < 8; b++) v[b] = glob[u + 256*b];
    fft8<false>(v);
    #pragma unroll
    for (int j = 1; j < 8; j++) v[j] = cmul(v[j], twid(1024, u*j));
    #pragma unroll
    for (int j = 0; j < 8; j++) sm[PAD(j*256 + u)] = v[j];
    __syncthreads();

    // S2: radix-8 over d (stride 32), twiddle W_256^{c*j2} (c*j2 <= 217 < 256)
    { const int j = u >> 5, c = u & 31, base = j*256 + c;
      #pragma unroll
      for (int d = 0; d < 8; d++) v[d] = sm[PAD(base + 32*d)];
      fft8<false>(v);
      #pragma unroll
      for (int j2 = 1; j2 < 8; j2++) v[j2] = cmul(v[j2], twid(128, c*j2));
      #pragma unroll
      for (int j2 = 0; j2 < 8; j2++) sm[PAD(j*256 + j2*32 + c)] = v[j2];
    }
    __syncthreads();

    // S3: radix-8 over f (stride 4), twiddle W_32^{e*j3} (e*j3 <= 21 < 32)
    { const int j = u >> 5, j2 = (u >> 2) & 7, e = u & 3, base = j*256 + j2*32 + e;
      #pragma unroll
      for (int f = 0; f < 8; f++) v[f] = sm[PAD(base + 4*f)];
      fft8<false>(v);
      #pragma unroll
      for (int j3 = 1; j3 < 8; j3++) v[j3] = cmul(v[j3], twid(16, e*j3));
      #pragma unroll
      for (int j3 = 0; j3 < 8; j3++) sm[PAD(j*256 + j2*32 + j3*4 + e)] = v[j3];
    }
    __syncthreads();

    // S4: radix-4 over e (stride 1); 2 groups per thread per row
    #pragma unroll
    for (int gi = 0; gi < 2; gi++) {
        const int grp = u + 256*gi;
        float2 w4[4];
        #pragma unroll
        for (int e = 0; e < 4; e++) w4[e] = sm[PAD(4*grp + e)];
        fft4<false>(w4);
        #pragma unroll
        for (int m = 0; m < 4; m++) sm[PAD(4*grp + m)] = w4[m];
    }
    __syncthreads();

    if (g != 0) {
        // pointwise fused with inverse radix-4, ROW A ONLY; all 512 threads
        // (thread t owns A-group t; smB is read-only from here on).
        float2 ya[4];
        #pragma unroll
        for (int e = 0; e < 4; e++) {
            float2 Za = smA[PAD(4*tid + e)];
            float2 Zb = smB[PAD(2047 - 4*tid - e)];
            ya[e] = pw(Za, Zb);
        }
        fft4<true>(ya);
        #pragma unroll
        for (int e = 0; e < 4; e++) smA[PAD(4*tid + e)] = ya[e];
    } else {
        // row 0 pairs with itself at k2' = (2048-k2) mod 2048 (k2-space);
        // row 32 self-pairs position-locally. Both rows stay (both <= 32).
        if (tid < 256) {
            #pragma unroll
            for (int e = 0; e < 4; e++) {
                int k2 = 4*tid + e;
                int pa = POS(k2);
                int pb = POS((2048 - k2) & 2047);
                float2 Za = smA[PAD(pa)];
                float2 Zb = smA[PAD(pb)];
                float2 Y = pw(Za, Zb);
                smA[PAD(pa)] = Y;
                smA[PAD(pb)] = cconj(Y);
            }
            if (tid == 0) {                      // k2 = 1024 self-pair, pos = 2
                float2 Za = smA[PAD(2)];
                smA[PAD(2)] = pw(Za, Za);
            }
        } else {
            const int u2 = tid - 256;
            #pragma unroll
            for (int e = 0; e < 4; e++) {
                int p = 4*u2 + e;
                float2 Za = smB[PAD(p)];
                float2 Zb = smB[PAD(2047 - p)];
                float2 Y = pw(Za, Zb);
                smB[PAD(p)]        = Y;
                smB[PAD(2047 - p)] = cconj(Y);
            }
        }
        __syncthreads();
        // IS4 separate (both rows)
        #pragma unroll
        for (int gi = 0; gi < 2; gi++) {
            const int grp = u + 256*gi;
            float2 w4[4];
            #pragma unroll
            for (int e = 0; e < 4; e++) w4[e] = sm[PAD(4*grp + e)];
            fft4<true>(w4);
            #pragma unroll
            for (int e = 0; e < 4; e++) sm[PAD(4*grp + e)] = w4[e];
        }
    }
    __syncthreads();

    // IS3: conj twiddle W_32^{-e*j3}, inverse radix-8 over j3 -> f
    if (r == 0 || invB) {
      const int j = u >> 5, j2 = (u >> 2) & 7, e = u & 3, base = j*256 + j2*32 + e;
      #pragma unroll
      for (int j3 = 0; j3 < 8; j3++) v[j3] = sm[PAD(base + 4*j3)];
      #pragma unroll
      for (int j3 = 1; j3 < 8; j3++) v[j3] = cmul(v[j3], twidc(16, e*j3));
      fft8<true>(v);
      #pragma unroll
      for (int f = 0; f < 8; f++) sm[PAD(base + 4*f)] = v[f];
    }
    __syncthreads();

    // IS2: conj twiddle W_256^{-c*j2}, inverse radix-8 over j2 -> d
    if (r == 0 || invB) {
      const int j = u >> 5, c = u & 31, base = j*256 + c;
      #pragma unroll
      for (int j2 = 0; j2 < 8; j2++) v[j2] = sm[PAD(base + 32*j2)];
      #pragma unroll
      for (int j2 = 1; j2 < 8; j2++) v[j2] = cmul(v[j2], twidc(128, c*j2));
      fft8<true>(v);
      #pragma unroll
      for (int d = 0; d < 8; d++) sm[PAD(base + 32*d)] = v[d];
    }
    __syncthreads();

    // IS1: conj twiddle W_2048^{-u*j}, inverse radix-8 over j -> b,
    // conj inter-step twiddle W_N^{-row*(b*256+a)}, store (rows <= 32 only).
    if (r == 0 || invB) {
      const int a = u;
      #pragma unroll
      for (int j = 0; j < 8; j++) v[j] = sm[PAD(j*256 + a)];
      #pragma unroll
      for (int j = 1; j < 8; j++) v[j] = cmul(v[j], twidc(1024, a*j));
      fft8<true>(v);
      int q = myrow * a;                        // <= 32*255, final <= 65504
      const int step = 256 * myrow;
      #pragma unroll
      for (int b = 0; b < 8; b++) {
          glob[b*256 + a] = cmul(v[b], twidc(NHALF, q));
          q += step;
      }
    }
}

// ---------------------------------------------------------------------------
// Stage 3: inverse 64-pt FFT along k1 (two register radix-8 passes, one smem
// exchange), scale 1/N, write real part of n1 < 32 only. Rows 33..63 are
// reconstructed as conj(row 64-r) — never read from DRAM.
// ---------------------------------------------------------------------------
__global__ void __launch_bounds__(256) k_stage3(float* __restrict__ out) {
    __shared__ float2 sm[64 * 32];
    const int s   = blockIdx.y;
    const int col = threadIdx.x & 31;
    const int j   = threadIdx.x >> 5;
    const int n2  = blockIdx.x * 32 + col;
    float2* zs = g_z + (size_t)s * NN;

    float2 v[8];
    #pragma unroll
    for (int m = 0; m < 8; m++) {
        int rr = j + 8*m;
        if (rr <= 32) {
            v[m] = zs[rr * N2 + n2];
        } else {
            v[m] = cconj(zs[(64 - rr) * N2 + n2]);
        }
    }
    fft8<true>(v);                               // over m -> a
    #pragma unroll
    for (int a = 0; a < 8; a++) sm[(a*8 + j)*32 + col] = v[a];
    __syncthreads();

    const int a = threadIdx.x >> 5;
    #pragma unroll
    for (int q = 0; q < 8; q++) v[q] = sm[(a*8 + q)*32 + col];
    #pragma unroll
    for (int q = 1; q < 8; q++) v[q] = cmul(v[q], twidc(32, a*q));
    fft8<true>(v);                               // over j -> b ; n1 = a + 8b

    const float sc = 1.0f / (float)NN;
    float* os = out + (size_t)s * T_LEN;
    #pragma unroll
    for (int b = 0; b < 4; b++)
        os[(a + 8*b) * N2 + n2] = v[b].x * sc;
}

extern "C" void kernel_launch(void* const* d_in, const int* in_sizes, int n_in,
                              void* d_out, int out_size) {
    const float* x = (const float*)d_in[0];
    const float* h = (const float*)d_in[1];
    float* out = (float*)d_out;

    k_init_tw<<<NN / 256, 256>>>();
    k_stage1<<<dim3(N2 / 32, SEQ), 256>>>(x, h);
    k_stage2<<<dim3(32, SEQ), 512>>>();
    k_stage3<<<dim3(N2 / 32, SEQ), 256>>>(out);
}

// round 6
// speedup vs baseline: 1.5986x; 1.5986x over previous
#include <cuda_runtime.h>
#include <cuda_bf16.h>

#define SEQ   512
#define T_LEN 65536
#define NN    131072
#define NHALF 65536
#define N2    2048

// Scratch (device globals; no allocations allowed)
__device__ float2 g_z[(size_t)SEQ * NN];   // 512 MiB workspace
__device__ float2 g_tw[NN];                // g_tw[h+p] = exp(-i*pi*p/h)

static __device__ __forceinline__ float2 cmul(float2 a, float2 b) {
    return make_float2(fmaf(a.x, b.x, -a.y * b.y), fmaf(a.x, b.y, a.y * b.x));
}
static __device__ __forceinline__ float2 cadd(float2 a, float2 b) { return make_float2(a.x+b.x, a.y+b.y); }
static __device__ __forceinline__ float2 csub(float2 a, float2 b) { return make_float2(a.x-b.x, a.y-b.y); }
static __device__ __forceinline__ float2 mulnI(float2 a) { return make_float2(a.y, -a.x); }   // * (-i)
static __device__ __forceinline__ float2 mulpI(float2 a) { return make_float2(-a.y, a.x); }   // * (+i)
static __device__ __forceinline__ float2 cconj(float2 a) { return make_float2(a.x, -a.y); }

// W_{2*Mhalf}^q  for q in [0, 2*Mhalf)
static __device__ __forceinline__ float2 twid(int Mhalf, int q) {
    if (q < Mhalf) return g_tw[Mhalf + q];
    float2 t = g_tw[q];                    // == g_tw[Mhalf + (q - Mhalf)]
    return make_float2(-t.x, -t.y);
}
// conj(W_{2*Mhalf}^q)
static __device__ __forceinline__ float2 twidc(int Mhalf, int q) {
    if (q < Mhalf) { float2 t = g_tw[Mhalf + q]; return make_float2(t.x, -t.y); }
    float2 t = g_tw[q];
    return make_float2(-t.x, t.y);
}

// Powers W[j] = w^j, j=1..7, built with a depth-3 tree (6 cmuls, 1 load).
static __device__ __forceinline__ void twpow(float2 W[8], float2 w) {
    W[1] = w;
    W[2] = cmul(w, w);
    W[3] = cmul(W[2], w);
    W[4] = cmul(W[2], W[2]);
    W[5] = cmul(W[2], W[3]);
    W[6] = cmul(W[3], W[3]);
    W[7] = cmul(W[3], W[4]);
}

// 8-pt DFT, natural in/out. INV => conjugated twiddles (unnormalized inverse).
template<bool INV>
static __device__ __forceinline__ void fft8(float2 z[8]) {
    const float C = 0.70710678118654752440f;
    float2 t0=cadd(z[0],z[4]), t1=cadd(z[1],z[5]), t2=cadd(z[2],z[6]), t3=cadd(z[3],z[7]);
    float2 s0=csub(z[0],z[4]), s1=csub(z[1],z[5]), s2=csub(z[2],z[6]), s3=csub(z[3],z[7]);
    if (!INV) {
        s1 = cmul(s1, make_float2(C,-C)); s2 = mulnI(s2); s3 = cmul(s3, make_float2(-C,-C));
    } else {
        s1 = cmul(s1, make_float2(C, C)); s2 = mulpI(s2); s3 = cmul(s3, make_float2(-C, C));
    }
    float2 a0=cadd(t0,t2), a1=csub(t0,t2), a2=cadd(t1,t3), a3=csub(t1,t3);
    a3 = INV ? mulpI(a3) : mulnI(a3);
    float2 b0=cadd(s0,s2), b1=csub(s0,s2), b2=cadd(s1,s3), b3=csub(s1,s3);
    b3 = INV ? mulpI(b3) : mulnI(b3);
    z[0]=cadd(a0,a2); z[4]=csub(a0,a2);
    z[2]=cadd(a1,a3); z[6]=csub(a1,a3);
    z[1]=cadd(b0,b2); z[5]=csub(b0,b2);
    z[3]=cadd(b1,b3); z[7]=csub(b1,b3);
}

template<bool INV>
static __device__ __forceinline__ void fft4(float2 z[4]) {
    float2 a0=cadd(z[0],z[2]), a1=csub(z[0],z[2]);
    float2 a2=cadd(z[1],z[3]), a3=csub(z[1],z[3]);
    a3 = INV ? mulpI(a3) : mulnI(a3);
    z[0]=cadd(a0,a2); z[2]=csub(a0,a2);
    z[1]=cadd(a1,a3); z[3]=csub(a1,a3);
}

// Hermitian unpack + pointwise: Za = Z[k], Zb = Z[N-k]; returns Y[k] = X[k]*H[k]
static __device__ __forceinline__ float2 pw(float2 Za, float2 Zb) {
    float2 X = make_float2(0.5f*(Za.x+Zb.x),  0.5f*(Za.y-Zb.y));
    float2 H = make_float2(0.5f*(Za.y+Zb.y), -0.5f*(Za.x-Zb.x));
    return cmul(X, H);
}

#define PAD(p) ((p) + (((p) >> 5) << 2))
#define POS(k2) ((((k2)&7)<<8) + ((((k2)>>3)&7)<<5) + ((((k2)>>6)&7)<<2) + ((k2)>>9))

__global__ void k_init_tw() {
    int idx = blockIdx.x * blockDim.x + threadIdx.x;
    if (idx >= NN) return;
    if (idx == 0) { g_tw[0] = make_float2(1.0f, 0.0f); return; }
    int h = 1 << (31 - __clz(idx));
    int p = idx - h;
    float s, c;
    sincospif(-(float)p / (float)h, &s, &c);
    g_tw[idx] = make_float2(c, s);
}

// ---------------------------------------------------------------------------
// Stage 1: pack z = bf16(x) + i*h (rows n1>=32 are zero) + 64-pt FFT along n1
// (two register radix-8 passes, one smem exchange) + twiddle W_N^{k1*n2}.
// Output: g_z[s][k1*2048 + n2]
// ---------------------------------------------------------------------------
__global__ void __launch_bounds__(256) k_stage1(const float* __restrict__ x,
                                                const float* __restrict__ hk) {
    __shared__ float2 sm[64 * 32];
    const int s   = blockIdx.y;
    const int col = threadIdx.x & 31;
    const int a   = threadIdx.x >> 5;          // 0..7
    const int n2  = blockIdx.x * 32 + col;
    const float* xs = x  + (size_t)s * T_LEN;
    const float* hs = hk + (size_t)s * T_LEN;

    float2 v[8];
    #pragma unroll
    for (int b = 0; b < 4; b++) {
        int n = (a + 8*b) * N2 + n2;           // < 65536 always
        v[b] = make_float2(__bfloat162float(__float2bfloat16_rn(xs[n])), hs[n]);
    }
    // fft8 over b with upper half zero (t = z, s = z)
    {
        const float C = 0.70710678118654752440f;
        float2 t0=v[0], t1=v[1], t2=v[2], t3=v[3];
        float2 s0=v[0];
        float2 s1=cmul(v[1], make_float2(C,-C));
        float2 s2=mulnI(v[2]);
        float2 s3=cmul(v[3], make_float2(-C,-C));
        float2 a0=cadd(t0,t2), a1=csub(t0,t2), a2=cadd(t1,t3), a3=mulnI(csub(t1,t3));
        float2 b0=cadd(s0,s2), b1=csub(s0,s2), b2=cadd(s1,s3), b3=mulnI(csub(s1,s3));
        v[0]=cadd(a0,a2); v[4]=csub(a0,a2);
        v[2]=cadd(a1,a3); v[6]=csub(a1,a3);
        v[1]=cadd(b0,b2); v[5]=csub(b0,b2);
        v[3]=cadd(b1,b3); v[7]=csub(b1,b3);
    }
    // twiddle W_64^{a*j}
    {
        float2 W[8];
        twpow(W, twid(32, a));
        #pragma unroll
        for (int j = 1; j < 8; j++) v[j] = cmul(v[j], W[j]);
    }
    #pragma unroll
    for (int j = 0; j < 8; j++) sm[(j*8 + a)*32 + col] = v[j];
    __syncthreads();

    const int j = a;                            // phase-2 role
    #pragma unroll
    for (int q = 0; q < 8; q++) v[q] = sm[(j*8 + q)*32 + col];
    fft8<false>(v);                             // over a -> m ; k1 = j + 8m

    float2* zs = g_z + (size_t)s * NN;
    {
        float2 acc  = twid(NHALF, n2 * j);      // n2*j < 65536
        float2 step = twid(NHALF, 8 * n2);
        #pragma unroll
        for (int m = 0; m < 8; m++) {
            int k1 = j + 8*m;
            zs[k1 * N2 + n2] = cmul(v[m], acc);
            acc = cmul(acc, step);
        }
    }
}

// ---------------------------------------------------------------------------
// Stage 2 (256 threads/block): pair {g, 64-g} ({0,32} for g==0).
// Each thread carries BOTH rows' butterfly groups through the forward stages
// (twiddles built once, applied to both -> 2x ILP, half the twiddle math).
// Inverse runs on row A only (realness: u[64-k1] = conj(u[k1]) after the conj
// inter-twiddle) with ALL 256 threads; g==0 inverts both rows 0 and 32.
// Stores rows 0..32 only.
// ---------------------------------------------------------------------------
__global__ void __launch_bounds__(256, 2) k_stage2() {
    __shared__ float2 smA[2304];
    __shared__ float2 smB[2304];
    const int s = blockIdx.y;
    const int g = blockIdx.x;                   // 0..31
    const int rowA = g;
    const int rowB = (g == 0) ? 32 : 64 - g;
    const int u = threadIdx.x;                  // 0..255
    const bool both = (g == 0);                 // inverse path needed for row B?
    float2* zs = g_z + (size_t)s * NN;
    float2* gA = zs + rowA * N2;
    float2* gB = zs + rowB * N2;

    float2 va[8], vb[8], W[8];

    // S1: radix-8 over b (stride 256), twiddle W_2048^{u*j}
    #pragma unroll
    for (int b = 0; b < 8; b++) { va[b] = gA[u + 256*b]; vb[b] = gB[u + 256*b]; }
    fft8<false>(va); fft8<false>(vb);
    twpow(W, twid(1024, u));
    #pragma unroll
    for (int j = 1; j < 8; j++) { va[j] = cmul(va[j], W[j]); vb[j] = cmul(vb[j], W[j]); }
    #pragma unroll
    for (int j = 0; j < 8; j++) { smA[PAD(j*256 + u)] = va[j]; smB[PAD(j*256 + u)] = vb[j]; }
    __syncthreads();

    // S2: radix-8 over d (stride 32), twiddle W_256^{c*j2}
    { const int j = u >> 5, c = u & 31, base = j*256 + c;
      #pragma unroll
      for (int d = 0; d < 8; d++) { va[d] = smA[PAD(base + 32*d)]; vb[d] = smB[PAD(base + 32*d)]; }
      fft8<false>(va); fft8<false>(vb);
      twpow(W, twid(128, c));
      #pragma unroll
      for (int j2 = 1; j2 < 8; j2++) { va[j2] = cmul(va[j2], W[j2]); vb[j2] = cmul(vb[j2], W[j2]); }
      #pragma unroll
      for (int j2 = 0; j2 < 8; j2++) { smA[PAD(j*256 + j2*32 + c)] = va[j2]; smB[PAD(j*256 + j2*32 + c)] = vb[j2]; }
    }
    __syncthreads();

    // S3: radix-8 over f (stride 4), twiddle W_32^{e*j3}
    { const int j = u >> 5, j2 = (u >> 2) & 7, e = u & 3, base = j*256 + j2*32 + e;
      #pragma unroll
      for (int f = 0; f < 8; f++) { va[f] = smA[PAD(base + 4*f)]; vb[f] = smB[PAD(base + 4*f)]; }
      fft8<false>(va); fft8<false>(vb);
      twpow(W, twid(16, e));
      #pragma unroll
      for (int j3 = 1; j3 < 8; j3++) { va[j3] = cmul(va[j3], W[j3]); vb[j3] = cmul(vb[j3], W[j3]); }
      #pragma unroll
      for (int j3 = 0; j3 < 8; j3++) { smA[PAD(base + 4*j3)] = va[j3]; smB[PAD(base + 4*j3)] = vb[j3]; }
    }
    __syncthreads();

    // S4: radix-4 over e (stride 1); 2 groups per thread per row
    #pragma unroll
    for (int gi = 0; gi < 2; gi++) {
        const int grp = u + 256*gi;
        float2 wa[4], wb[4];
        #pragma unroll
        for (int e = 0; e < 4; e++) { wa[e] = smA[PAD(4*grp + e)]; wb[e] = smB[PAD(4*grp + e)]; }
        fft4<false>(wa); fft4<false>(wb);
        #pragma unroll
        for (int e = 0; e < 4; e++) { smA[PAD(4*grp + e)] = wa[e]; smB[PAD(4*grp + e)] = wb[e]; }
    }
    __syncthreads();

    if (g != 0) {
        // pointwise fused with inverse radix-4, ROW A ONLY; 2 groups/thread.
        // smB is read-only from here; each thread writes only its own smA groups.
        #pragma unroll
        for (int gi = 0; gi < 2; gi++) {
            const int t = u + 256*gi;
            float2 ya[4];
            #pragma unroll
            for (int e = 0; e < 4; e++) {
                float2 Za = smA[PAD(4*t + e)];
                float2 Zb = smB[PAD(2047 - 4*t - e)];
                ya[e] = pw(Za, Zb);
            }
            fft4<true>(ya);
            #pragma unroll
            for (int e = 0; e < 4; e++) smA[PAD(4*t + e)] = ya[e];
        }
    } else {
        // row 0 pairs with itself at k2' = (2048-k2) mod 2048 (k2-space);
        // row 32 self-pairs position-locally. Both rows stay (both <= 32).
        #pragma unroll
        for (int e = 0; e < 4; e++) {
            int k2 = 4*u + e;                    // 0..1023
            int pa = POS(k2);
            int pb = POS((2048 - k2) & 2047);
            float2 Za = smA[PAD(pa)];
            float2 Zb = smA[PAD(pb)];
            float2 Y = pw(Za, Zb);
            smA[PAD(pa)] = Y;
            smA[PAD(pb)] = cconj(Y);
        }
        if (u == 0) {                            // k2 = 1024 self-pair, pos = 2
            float2 Za = smA[PAD(2)];
            smA[PAD(2)] = pw(Za, Za);
        }
        #pragma unroll
        for (int e = 0; e < 4; e++) {
            int p = 4*u + e;                     // 0..1023
            float2 Za = smB[PAD(p)];
            float2 Zb = smB[PAD(2047 - p)];
            float2 Y = pw(Za, Zb);
            smB[PAD(p)]        = Y;
            smB[PAD(2047 - p)] = cconj(Y);
        }
        __syncthreads();
        // IS4 separate (both rows)
        #pragma unroll
        for (int gi = 0; gi < 2; gi++) {
            const int grp = u + 256*gi;
            float2 wa[4], wb[4];
            #pragma unroll
            for (int e = 0; e < 4; e++) { wa[e] = smA[PAD(4*grp + e)]; wb[e] = smB[PAD(4*grp + e)]; }
            fft4<true>(wa); fft4<true>(wb);
            #pragma unroll
            for (int e = 0; e < 4; e++) { smA[PAD(4*grp + e)] = wa[e]; smB[PAD(4*grp + e)] = wb[e]; }
        }
    }
    __syncthreads();

    // IS3: conj twiddle W_32^{-e*j3}, inverse radix-8 over j3 -> f
    { const int j = u >> 5, j2 = (u >> 2) & 7, e = u & 3, base = j*256 + j2*32 + e;
      #pragma unroll
      for (int j3 = 0; j3 < 8; j3++) va[j3] = smA[PAD(base + 4*j3)];
      twpow(W, twidc(16, e));
      #pragma unroll
      for (int j3 = 1; j3 < 8; j3++) va[j3] = cmul(va[j3], W[j3]);
      fft8<true>(va);
      if (both) {
          #pragma unroll
          for (int j3 = 0; j3 < 8; j3++) vb[j3] = smB[PAD(base + 4*j3)];
          #pragma unroll
          for (int j3 = 1; j3 < 8; j3++) vb[j3] = cmul(vb[j3], W[j3]);
          fft8<true>(vb);
      }
      __syncthreads();
      #pragma unroll
      for (int f = 0; f < 8; f++) smA[PAD(base + 4*f)] = va[f];
      if (both) {
          #pragma unroll
          for (int f = 0; f < 8; f++) smB[PAD(base + 4*f)] = vb[f];
      }
    }
    __syncthreads();

    // IS2: conj twiddle W_256^{-c*j2}, inverse radix-8 over j2 -> d
    { const int j = u >> 5, c = u & 31, base = j*256 + c;
      #pragma unroll
      for (int j2 = 0; j2 < 8; j2++) va[j2] = smA[PAD(base + 32*j2)];
      twpow(W, twidc(128, c));
      #pragma unroll
      for (int j2 = 1; j2 < 8; j2++) va[j2] = cmul(va[j2], W[j2]);
      fft8<true>(va);
      if (both) {
          #pragma unroll
          for (int j2 = 0; j2 < 8; j2++) vb[j2] = smB[PAD(base + 32*j2)];
          #pragma unroll
          for (int j2 = 1; j2 < 8; j2++) vb[j2] = cmul(vb[j2], W[j2]);
          fft8<true>(vb);
      }
      __syncthreads();
      #pragma unroll
      for (int d = 0; d < 8; d++) smA[PAD(base + 32*d)] = va[d];
      if (both) {
          #pragma unroll
          for (int d = 0; d < 8; d++) smB[PAD(base + 32*d)] = vb[d];
      }
    }
    __syncthreads();

    // IS1: conj twiddle W_2048^{-a*j}, inverse radix-8 over j -> b,
    // conj inter-step twiddle W_N^{-row*(b*256+a)}, store (rows <= 32 only).
    { const int a = u;
      #pragma unroll
      for (int j = 0; j < 8; j++) va[j] = smA[PAD(j*256 + a)];
      twpow(W, twidc(1024, a));
      #pragma unroll
      for (int j = 1; j < 8; j++) va[j] = cmul(va[j], W[j]);
      fft8<true>(va);
      { float2 acc  = twidc(NHALF, rowA * a);
        float2 step = twidc(NHALF, 256 * rowA);
        #pragma unroll
        for (int b = 0; b < 8; b++) {
            gA[b*256 + a] = cmul(va[b], acc);
            acc = cmul(acc, step);
        }
      }
      if (both) {
          #pragma unroll
          for (int j = 0; j < 8; j++) vb[j] = smB[PAD(j*256 + a)];
          #pragma unroll
          for (int j = 1; j < 8; j++) vb[j] = cmul(vb[j], W[j]);
          fft8<true>(vb);
          float2 acc  = twidc(NHALF, rowB * a);
          float2 step = twidc(NHALF, 256 * rowB);
          #pragma unroll
          for (int b = 0; b < 8; b++) {
              gB[b*256 + a] = cmul(vb[b], acc);
              acc = cmul(acc, step);
          }
      }
    }
}

// ---------------------------------------------------------------------------
// Stage 3: inverse 64-pt FFT along k1 (two register radix-8 passes, one smem
// exchange), scale 1/N, write real part of n1 < 32 only. Rows 33..63 are
// reconstructed as conj(row 64-r) — never read from DRAM.
// ---------------------------------------------------------------------------
__global__ void __launch_bounds__(256) k_stage3(float* __restrict__ out) {
    __shared__ float2 sm[64 * 32];
    const int s   = blockIdx.y;
    const int col = threadIdx.x & 31;
    const int j   = threadIdx.x >> 5;
    const int n2  = blockIdx.x * 32 + col;
    float2* zs = g_z + (size_t)s * NN;

    float2 v[8];
    #pragma unroll
    for (int m = 0; m < 8; m++) {
        int rr = j + 8*m;
        if (rr <= 32) {
            v[m] = zs[rr * N2 + n2];
        } else {
            v[m] = cconj(zs[(64 - rr) * N2 + n2]);
        }
    }
    fft8<true>(v);                               // over m -> a
    #pragma unroll
    for (int a = 0; a < 8; a++) sm[(a*8 + j)*32 + col] = v[a];
    __syncthreads();

    const int a = threadIdx.x >> 5;
    #pragma unroll
    for (int q = 0; q < 8; q++) v[q] = sm[(a*8 + q)*32 + col];
    { float2 W[8];
      twpow(W, twidc(32, a));
      #pragma unroll
      for (int q = 1; q < 8; q++) v[q] = cmul(v[q], W[q]);
    }
    fft8<true>(v);                               // over j -> b ; n1 = a + 8b

    const float sc = 1.0f / (float)NN;
    float* os = out + (size_t)s * T_LEN;
    #pragma unroll
    for (int b = 0; b < 4; b++)
        os[(a + 8*b) * N2 + n2] = v[b].x * sc;
}

extern "C" void kernel_launch(void* const* d_in, const int* in_sizes, int n_in,
                              void* d_out, int out_size) {
    const float* x = (const float*)d_in[0];
    const float* h = (const float*)d_in[1];
    float* out = (float*)d_out;

    k_init_tw<<<NN / 256, 256>>>();
    k_stage1<<<dim3(N2 / 32, SEQ), 256>>>(x, h);
    k_stage2<<<dim3(32, SEQ), 256>>>();
    k_stage3<<<dim3(N2 / 32, SEQ), 256>>>(out);
}

// round 8
// speedup vs baseline: 1.6882x; 1.0560x over previous
#include <cuda_runtime.h>
#include <cuda_bf16.h>

#define SEQ   512
#define T_LEN 65536
#define NN    131072
#define NHALF 65536
#define N2    2048

// Scratch (device globals; no allocations allowed)
__device__ float2 g_z[(size_t)SEQ * NN];   // 512 MiB workspace
__device__ float2 g_tw[NN];                // g_tw[h+p] = exp(-i*pi*p/h)

static __device__ __forceinline__ float2 cmul(float2 a, float2 b) {
    return make_float2(fmaf(a.x, b.x, -a.y * b.y), fmaf(a.x, b.y, a.y * b.x));
}
static __device__ __forceinline__ float2 cadd(float2 a, float2 b) { return make_float2(a.x+b.x, a.y+b.y); }
static __device__ __forceinline__ float2 csub(float2 a, float2 b) { return make_float2(a.x-b.x, a.y-b.y); }
static __device__ __forceinline__ float2 mulnI(float2 a) { return make_float2(a.y, -a.x); }   // * (-i)
static __device__ __forceinline__ float2 mulpI(float2 a) { return make_float2(-a.y, a.x); }   // * (+i)
static __device__ __forceinline__ float2 cconj(float2 a) { return make_float2(a.x, -a.y); }

// W_{2*Mhalf}^q  for q in [0, 2*Mhalf)
static __device__ __forceinline__ float2 twid(int Mhalf, int q) {
    if (q < Mhalf) return g_tw[Mhalf + q];
    float2 t = g_tw[q];                    // == g_tw[Mhalf + (q - Mhalf)]
    return make_float2(-t.x, -t.y);
}
// conj(W_{2*Mhalf}^q)
static __device__ __forceinline__ float2 twidc(int Mhalf, int q) {
    if (q < Mhalf) { float2 t = g_tw[Mhalf + q]; return make_float2(t.x, -t.y); }
    float2 t = g_tw[q];
    return make_float2(-t.x, t.y);
}

// Powers W[j] = w^j, j=1..7, built with a depth-3 tree (6 cmuls, 1 load).
static __device__ __forceinline__ void twpow(float2 W[8], float2 w) {
    W[1] = w;
    W[2] = cmul(w, w);
    W[3] = cmul(W[2], w);
    W[4] = cmul(W[2], W[2]);
    W[5] = cmul(W[2], W[3]);
    W[6] = cmul(W[3], W[3]);
    W[7] = cmul(W[3], W[4]);
}

// 8-pt DFT, natural in/out. INV => conjugated twiddles (unnormalized inverse).
template<bool INV>
static __device__ __forceinline__ void fft8(float2 z[8]) {
    const float C = 0.70710678118654752440f;
    float2 t0=cadd(z[0],z[4]), t1=cadd(z[1],z[5]), t2=cadd(z[2],z[6]), t3=cadd(z[3],z[7]);
    float2 s0=csub(z[0],z[4]), s1=csub(z[1],z[5]), s2=csub(z[2],z[6]), s3=csub(z[3],z[7]);
    if (!INV) {
        s1 = cmul(s1, make_float2(C,-C)); s2 = mulnI(s2); s3 = cmul(s3, make_float2(-C,-C));
    } else {
        s1 = cmul(s1, make_float2(C, C)); s2 = mulpI(s2); s3 = cmul(s3, make_float2(-C, C));
    }
    float2 a0=cadd(t0,t2), a1=csub(t0,t2), a2=cadd(t1,t3), a3=csub(t1,t3);
    a3 = INV ? mulpI(a3) : mulnI(a3);
    float2 b0=cadd(s0,s2), b1=csub(s0,s2), b2=cadd(s1,s3), b3=csub(s1,s3);
    b3 = INV ? mulpI(b3) : mulnI(b3);
    z[0]=cadd(a0,a2); z[4]=csub(a0,a2);
    z[2]=cadd(a1,a3); z[6]=csub(a1,a3);
    z[1]=cadd(b0,b2); z[5]=csub(b0,b2);
    z[3]=cadd(b1,b3); z[7]=csub(b1,b3);
}

template<bool INV>
static __device__ __forceinline__ void fft4(float2 z[4]) {
    float2 a0=cadd(z[0],z[2]), a1=csub(z[0],z[2]);
    float2 a2=cadd(z[1],z[3]), a3=csub(z[1],z[3]);
    a3 = INV ? mulpI(a3) : mulnI(a3);
    z[0]=cadd(a0,a2); z[2]=csub(a0,a2);
    z[1]=cadd(a1,a3); z[3]=csub(a1,a3);
}

// Hermitian unpack + pointwise: Za = Z[k], Zb = Z[N-k]; returns Y[k] = X[k]*H[k]
static __device__ __forceinline__ float2 pw(float2 Za, float2 Zb) {
    float2 X = make_float2(0.5f*(Za.x+Zb.x),  0.5f*(Za.y-Zb.y));
    float2 H = make_float2(0.5f*(Za.y+Zb.y), -0.5f*(Za.x-Zb.x));
    return cmul(X, H);
}

#define PAD(p) ((p) + (((p) >> 5) << 2))
#define POS(k2) ((((k2)&7)<<8) + ((((k2)>>3)&7)<<5) + ((((k2)>>6)&7)<<2) + ((k2)>>9))

__global__ void k_init_tw() {
    int idx = blockIdx.x * blockDim.x + threadIdx.x;
    if (idx >= NN) return;
    if (idx == 0) { g_tw[0] = make_float2(1.0f, 0.0f); return; }
    int h = 1 << (31 - __clz(idx));
    int p = idx - h;
    float s, c;
    sincospif(-(float)p / (float)h, &s, &c);
    g_tw[idx] = make_float2(c, s);
}

// ---------------------------------------------------------------------------
// Stage 1: pack z = bf16(x) + i*h (rows n1>=32 are zero) + 64-pt FFT along n1
// (two register radix-8 passes, one smem exchange) + twiddle W_N^{k1*n2}.
// Output: g_z[s][k1*2048 + n2]
// ---------------------------------------------------------------------------
__global__ void __launch_bounds__(256) k_stage1(const float* __restrict__ x,
                                                const float* __restrict__ hk) {
    __shared__ float2 sm[64 * 32];
    const int s   = blockIdx.y;
    const int col = threadIdx.x & 31;
    const int a   = threadIdx.x >> 5;          // 0..7
    const int n2  = blockIdx.x * 32 + col;
    const float* xs = x  + (size_t)s * T_LEN;
    const float* hs = hk + (size_t)s * T_LEN;

    float2 v[8];
    #pragma unroll
    for (int b = 0; b < 4; b++) {
        int n = (a + 8*b) * N2 + n2;           // < 65536 always
        v[b] = make_float2(__bfloat162float(__float2bfloat16_rn(xs[n])), hs[n]);
    }
    // fft8 over b with upper half zero (t = z, s = z)
    {
        const float C = 0.70710678118654752440f;
        float2 t0=v[0], t1=v[1], t2=v[2], t3=v[3];
        float2 s0=v[0];
        float2 s1=cmul(v[1], make_float2(C,-C));
        float2 s2=mulnI(v[2]);
        float2 s3=cmul(v[3], make_float2(-C,-C));
        float2 a0=cadd(t0,t2), a1=csub(t0,t2), a2=cadd(t1,t3), a3=mulnI(csub(t1,t3));
        float2 b0=cadd(s0,s2), b1=csub(s0,s2), b2=cadd(s1,s3), b3=mulnI(csub(s1,s3));
        v[0]=cadd(a0,a2); v[4]=csub(a0,a2);
        v[2]=cadd(a1,a3); v[6]=csub(a1,a3);
        v[1]=cadd(b0,b2); v[5]=csub(b0,b2);
        v[3]=cadd(b1,b3); v[7]=csub(b1,b3);
    }
    // twiddle W_64^{a*j}
    {
        float2 W[8];
        twpow(W, twid(32, a));
        #pragma unroll
        for (int j = 1; j < 8; j++) v[j] = cmul(v[j], W[j]);
    }
    #pragma unroll
    for (int j = 0; j < 8; j++) sm[(j*8 + a)*32 + col] = v[j];
    __syncthreads();

    const int j = a;                            // phase-2 role
    #pragma unroll
    for (int q = 0; q < 8; q++) v[q] = sm[(j*8 + q)*32 + col];
    fft8<false>(v);                             // over a -> m ; k1 = j + 8m

    float2* zs = g_z + (size_t)s * NN;
    {
        float2 acc  = twid(NHALF, n2 * j);      // n2*j < 65536
        float2 step = twid(NHALF, 8 * n2);
        #pragma unroll
        for (int m = 0; m < 8; m++) {
            int k1 = j + 8*m;
            zs[k1 * N2 + n2] = cmul(v[m], acc);
            acc = cmul(acc, step);
        }
    }
}

// ---------------------------------------------------------------------------
// Stage 2 (512 threads, 2 blocks/SM): pair {g, 64-g} ({0,32} for g==0):
//   fwd FFT-2048 both rows (radix 8,8,8,4; digit-reversed positions)
//   -> Hermitian pointwise (complement p <-> 2047-p is position-local)
//   -> inverse FFT-2048 for row A ONLY (output realness implies
//      u[64-k1] = conj(u[k1]) after the conj inter-twiddle, so rows > 32
//      are never materialized) -> store rows 0..32 only.
// Per-stage twiddles via depth-3 power trees (1 load + 6 independent cmuls).
// ---------------------------------------------------------------------------
__global__ void __launch_bounds__(512, 2) k_stage2() {
    __shared__ float2 smAB[2 * 2304];
    const int s = blockIdx.y;
    const int g = blockIdx.x;                   // 0..31
    const int rowA = g;
    const int rowB = (g == 0) ? 32 : 64 - g;
    const int tid = threadIdx.x;
    const int r = tid >> 8;                     // which row this thread serves
    const int u = tid & 255;
    const int myrow = r ? rowB : rowA;
    const bool invB = (g == 0);                 // does row B need the inverse path?
    float2* zs   = g_z + (size_t)s * NN;
    float2* glob = zs + myrow * N2;
    float2* sm   = smAB + r * 2304;
    float2* smA  = smAB;
    float2* smB  = smAB + 2304;

    float2 v[8], W[8];
    // S1: radix-8 over b (stride 256), twiddle W_2048^{u*j}
    #pragma unroll
    for (int b = 0; b < 8; b++) v[b] = glob[u + 256*b];
    fft8<false>(v);
    twpow(W, twid(1024, u));
    #pragma unroll
    for (int j = 1; j < 8; j++) v[j] = cmul(v[j], W[j]);
    #pragma unroll
    for (int j = 0; j < 8; j++) sm[PAD(j*256 + u)] = v[j];
    __syncthreads();

    // S2: radix-8 over d (stride 32), twiddle W_256^{c*j2}
    { const int j = u >> 5, c = u & 31, base = j*256 + c;
      #pragma unroll
      for (int d = 0; d < 8; d++) v[d] = sm[PAD(base + 32*d)];
      fft8<false>(v);
      twpow(W, twid(128, c));
      #pragma unroll
      for (int j2 = 1; j2 < 8; j2++) v[j2] = cmul(v[j2], W[j2]);
      #pragma unroll
      for (int j2 = 0; j2 < 8; j2++) sm[PAD(j*256 + j2*32 + c)] = v[j2];
    }
    __syncthreads();

    // S3: radix-8 over f (stride 4), twiddle W_32^{e*j3}
    { const int j = u >> 5, j2 = (u >> 2) & 7, e = u & 3, base = j*256 + j2*32 + e;
      #pragma unroll
      for (int f = 0; f < 8; f++) v[f] = sm[PAD(base + 4*f)];
      fft8<false>(v);
      twpow(W, twid(16, e));
      #pragma unroll
      for (int j3 = 1; j3 < 8; j3++) v[j3] = cmul(v[j3], W[j3]);
      #pragma unroll
      for (int j3 = 0; j3 < 8; j3++) sm[PAD(j*256 + j2*32 + j3*4 + e)] = v[j3];
    }
    __syncthreads();

    // S4: radix-4 over e (stride 1); 2 groups per thread per row
    #pragma unroll
    for (int gi = 0; gi < 2; gi++) {
        const int grp = u + 256*gi;
        float2 w4[4];
        #pragma unroll
        for (int e = 0; e < 4; e++) w4[e] = sm[PAD(4*grp + e)];
        fft4<false>(w4);
        #pragma unroll
        for (int m = 0; m < 4; m++) sm[PAD(4*grp + m)] = w4[m];
    }
    __syncthreads();

    if (g != 0) {
        // pointwise fused with inverse radix-4, ROW A ONLY; all 512 threads
        // (thread t owns A-group t; smB is read-only from here on).
        float2 ya[4];
        #pragma unroll
        for (int e = 0; e < 4; e++) {
            float2 Za = smA[PAD(4*tid + e)];
            float2 Zb = smB[PAD(2047 - 4*tid - e)];
            ya[e] = pw(Za, Zb);
        }
        fft4<true>(ya);
        #pragma unroll
        for (int e = 0; e < 4; e++) smA[PAD(4*tid + e)] = ya[e];
    } else {
        // row 0 pairs with itself at k2' = (2048-k2) mod 2048 (k2-space);
        // row 32 self-pairs position-locally. Both rows stay (both <= 32).
        if (tid < 256) {
            #pragma unroll
            for (int e = 0; e < 4; e++) {
                int k2 = 4*tid + e;
                int pa = POS(k2);
                int pb = POS((2048 - k2) & 2047);
                float2 Za = smA[PAD(pa)];
                float2 Zb = smA[PAD(pb)];
                float2 Y = pw(Za, Zb);
                smA[PAD(pa)] = Y;
                smA[PAD(pb)] = cconj(Y);
            }
            if (tid == 0) {                      // k2 = 1024 self-pair, pos = 2
                float2 Za = smA[PAD(2)];
                smA[PAD(2)] = pw(Za, Za);
            }
        } else {
            const int u2 = tid - 256;
            #pragma unroll
            for (int e = 0; e < 4; e++) {
                int p = 4*u2 + e;
                float2 Za = smB[PAD(p)];
                float2 Zb = smB[PAD(2047 - p)];
                float2 Y = pw(Za, Zb);
                smB[PAD(p)]        = Y;
                smB[PAD(2047 - p)] = cconj(Y);
            }
        }
        __syncthreads();
        // IS4 separate (both rows)
        #pragma unroll
        for (int gi = 0; gi < 2; gi++) {
            const int grp = u + 256*gi;
            float2 w4[4];
            #pragma unroll
            for (int e = 0; e < 4; e++) w4[e] = sm[PAD(4*grp + e)];
            fft4<true>(w4);
            #pragma unroll
            for (int e = 0; e < 4; e++) sm[PAD(4*grp + e)] = w4[e];
        }
    }
    __syncthreads();

    // IS3: conj twiddle W_32^{-e*j3}, inverse radix-8 over j3 -> f
    if (r == 0 || invB) {
      const int j = u >> 5, j2 = (u >> 2) & 7, e = u & 3, base = j*256 + j2*32 + e;
      #pragma unroll
      for (int j3 = 0; j3 < 8; j3++) v[j3] = sm[PAD(base + 4*j3)];
      twpow(W, twidc(16, e));
      #pragma unroll
      for (int j3 = 1; j3 < 8; j3++) v[j3] = cmul(v[j3], W[j3]);
      fft8<true>(v);
      #pragma unroll
      for (int f = 0; f < 8; f++) sm[PAD(base + 4*f)] = v[f];
    }
    __syncthreads();

    // IS2: conj twiddle W_256^{-c*j2}, inverse radix-8 over j2 -> d
    if (r == 0 || invB) {
      const int j = u >> 5, c = u & 31, base = j*256 + c;
      #pragma unroll
      for (int j2 = 0; j2 < 8; j2++) v[j2] = sm[PAD(base + 32*j2)];
      twpow(W, twidc(128, c));
      #pragma unroll
      for (int j2 = 1; j2 < 8; j2++) v[j2] = cmul(v[j2], W[j2]);
      fft8<true>(v);
      #pragma unroll
      for (int d = 0; d < 8; d++) sm[PAD(base + 32*d)] = v[d];
    }
    __syncthreads();

    // IS1: conj twiddle W_2048^{-a*j}, inverse radix-8 over j -> b,
    // conj inter-step twiddle W_N^{-row*(b*256+a)}, store (rows <= 32 only).
    if (r == 0 || invB) {
      const int a = u;
      #pragma unroll
      for (int j = 0; j < 8; j++) v[j] = sm[PAD(j*256 + a)];
      twpow(W, twidc(1024, a));
      #pragma unroll
      for (int j = 1; j < 8; j++) v[j] = cmul(v[j], W[j]);
      fft8<true>(v);
      float2 acc  = twidc(NHALF, myrow * a);
      float2 step = twidc(NHALF, 256 * myrow);
      #pragma unroll
      for (int b = 0; b < 8; b++) {
          glob[b*256 + a] = cmul(v[b], acc);
          acc = cmul(acc, step);
      }
    }
}

// ---------------------------------------------------------------------------
// Stage 3: inverse 64-pt FFT along k1 (two register radix-8 passes, one smem
// exchange), scale 1/N, write real part of n1 < 32 only. Rows 33..63 are
// reconstructed as conj(row 64-r) — never read from DRAM.
// ---------------------------------------------------------------------------
__global__ void __launch_bounds__(256) k_stage3(float* __restrict__ out) {
    __shared__ float2 sm[64 * 32];
    const int s   = blockIdx.y;
    const int col = threadIdx.x & 31;
    const int j   = threadIdx.x >> 5;
    const int n2  = blockIdx.x * 32 + col;
    float2* zs = g_z + (size_t)s * NN;

    float2 v[8];
    #pragma unroll
    for (int m = 0; m < 8; m++) {
        int rr = j + 8*m;
        if (rr <= 32) {
            v[m] = zs[rr * N2 + n2];
        } else {
            v[m] = cconj(zs[(64 - rr) * N2 + n2]);
        }
    }
    fft8<true>(v);                               // over m -> a
    #pragma unroll
    for (int a = 0; a < 8; a++) sm[(a*8 + j)*32 + col] = v[a];
    __syncthreads();

    const int a = threadIdx.x >> 5;
    #pragma unroll
    for (int q = 0; q < 8; q++) v[q] = sm[(a*8 + q)*32 + col];
    { float2 W[8];
      twpow(W, twidc(32, a));
      #pragma unroll
      for (int q = 1; q < 8; q++) v[q] = cmul(v[q], W[q]);
    }
    fft8<true>(v);                               // over j -> b ; n1 = a + 8b

    const float sc = 1.0f / (float)NN;
    float* os = out + (size_t)s * T_LEN;
    #pragma unroll
    for (int b = 0; b < 4; b++)
        os[(a + 8*b) * N2 + n2] = v[b].x * sc;
}

extern "C" void kernel_launch(void* const* d_in, const int* in_sizes, int n_in,
                              void* d_out, int out_size) {
    const float* x = (const float*)d_in[0];
    const float* h = (const float*)d_in[1];
    float* out = (float*)d_out;

    k_init_tw<<<NN / 256, 256>>>();
    k_stage1<<<dim3(N2 / 32, SEQ), 256>>>(x, h);
    k_stage2<<<dim3(32, SEQ), 512>>>();
    k_stage3<<<dim3(N2 / 32, SEQ), 256>>>(out);
}

// round 9
// speedup vs baseline: 1.9807x; 1.1733x over previous
#include <cuda_runtime.h>
#include <cuda_bf16.h>
#include <cuda_fp16.h>

#define SEQ   512
#define T_LEN 65536
#define NN    131072
#define NHALF 65536
#define N2    2048

// Scratch (device globals; no allocations allowed)
__device__ float2 g_z[(size_t)SEQ * NN];        // 512 MiB fp32 workspace
__device__ __half2 g_h[(size_t)SEQ * 33 * N2];  // 138 MiB fp16 stage2->3 buffer
__device__ float2 g_tw[NN];                     // g_tw[h+p] = exp(-i*pi*p/h)

static __device__ __forceinline__ float2 cmul(float2 a, float2 b) {
    return make_float2(fmaf(a.x, b.x, -a.y * b.y), fmaf(a.x, b.y, a.y * b.x));
}
static __device__ __forceinline__ float2 cadd(float2 a, float2 b) { return make_float2(a.x+b.x, a.y+b.y); }
static __device__ __forceinline__ float2 csub(float2 a, float2 b) { return make_float2(a.x-b.x, a.y-b.y); }
static __device__ __forceinline__ float2 mulnI(float2 a) { return make_float2(a.y, -a.x); }   // * (-i)
static __device__ __forceinline__ float2 mulpI(float2 a) { return make_float2(-a.y, a.x); }   // * (+i)
static __device__ __forceinline__ float2 cconj(float2 a) { return make_float2(a.x, -a.y); }

// W_{2*Mhalf}^q  for q in [0, 2*Mhalf)
static __device__ __forceinline__ float2 twid(int Mhalf, int q) {
    if (q < Mhalf) return g_tw[Mhalf + q];
    float2 t = g_tw[q];                    // == g_tw[Mhalf + (q - Mhalf)]
    return make_float2(-t.x, -t.y);
}
// conj(W_{2*Mhalf}^q)
static __device__ __forceinline__ float2 twidc(int Mhalf, int q) {
    if (q < Mhalf) { float2 t = g_tw[Mhalf + q]; return make_float2(t.x, -t.y); }
    float2 t = g_tw[q];
    return make_float2(-t.x, t.y);
}

// Powers W[j] = w^j, j=1..7, built with a depth-3 tree (6 cmuls, 1 load).
static __device__ __forceinline__ void twpow(float2 W[8], float2 w) {
    W[1] = w;
    W[2] = cmul(w, w);
    W[3] = cmul(W[2], w);
    W[4] = cmul(W[2], W[2]);
    W[5] = cmul(W[2], W[3]);
    W[6] = cmul(W[3], W[3]);
    W[7] = cmul(W[3], W[4]);
}

// 8-pt DFT, natural in/out. INV => conjugated twiddles (unnormalized inverse).
template<bool INV>
static __device__ __forceinline__ void fft8(float2 z[8]) {
    const float C = 0.70710678118654752440f;
    float2 t0=cadd(z[0],z[4]), t1=cadd(z[1],z[5]), t2=cadd(z[2],z[6]), t3=cadd(z[3],z[7]);
    float2 s0=csub(z[0],z[4]), s1=csub(z[1],z[5]), s2=csub(z[2],z[6]), s3=csub(z[3],z[7]);
    if (!INV) {
        s1 = cmul(s1, make_float2(C,-C)); s2 = mulnI(s2); s3 = cmul(s3, make_float2(-C,-C));
    } else {
        s1 = cmul(s1, make_float2(C, C)); s2 = mulpI(s2); s3 = cmul(s3, make_float2(-C, C));
    }
    float2 a0=cadd(t0,t2), a1=csub(t0,t2), a2=cadd(t1,t3), a3=csub(t1,t3);
    a3 = INV ? mulpI(a3) : mulnI(a3);
    float2 b0=cadd(s0,s2), b1=csub(s0,s2), b2=cadd(s1,s3), b3=csub(s1,s3);
    b3 = INV ? mulpI(b3) : mulnI(b3);
    z[0]=cadd(a0,a2); z[4]=csub(a0,a2);
    z[2]=cadd(a1,a3); z[6]=csub(a1,a3);
    z[1]=cadd(b0,b2); z[5]=csub(b0,b2);
    z[3]=cadd(b1,b3); z[7]=csub(b1,b3);
}

template<bool INV>
static __device__ __forceinline__ void fft4(float2 z[4]) {
    float2 a0=cadd(z[0],z[2]), a1=csub(z[0],z[2]);
    float2 a2=cadd(z[1],z[3]), a3=csub(z[1],z[3]);
    a3 = INV ? mulpI(a3) : mulnI(a3);
    z[0]=cadd(a0,a2); z[2]=csub(a0,a2);
    z[1]=cadd(a1,a3); z[3]=csub(a1,a3);
}

// Hermitian unpack + pointwise: Za = Z[k], Zb = Z[N-k]; returns Y[k] = X[k]*H[k]
static __device__ __forceinline__ float2 pw(float2 Za, float2 Zb) {
    float2 X = make_float2(0.5f*(Za.x+Zb.x),  0.5f*(Za.y-Zb.y));
    float2 H = make_float2(0.5f*(Za.y+Zb.y), -0.5f*(Za.x-Zb.x));
    return cmul(X, H);
}

#define PAD(p) ((p) + (((p) >> 5) << 2))
#define POS(k2) ((((k2)&7)<<8) + ((((k2)>>3)&7)<<5) + ((((k2)>>6)&7)<<2) + ((k2)>>9))

__global__ void k_init_tw() {
    int idx = blockIdx.x * blockDim.x + threadIdx.x;
    if (idx >= NN) return;
    if (idx == 0) { g_tw[0] = make_float2(1.0f, 0.0f); return; }
    int h = 1 << (31 - __clz(idx));
    int p = idx - h;
    float s, c;
    sincospif(-(float)p / (float)h, &s, &c);
    g_tw[idx] = make_float2(c, s);
}

// ---------------------------------------------------------------------------
// Stage 1: pack z = bf16(x) + i*h (rows n1>=32 are zero) + 64-pt FFT along n1
// (two register radix-8 passes, one smem exchange) + twiddle W_N^{k1*n2}.
// Output: g_z[s][k1*2048 + n2]
// ---------------------------------------------------------------------------
__global__ void __launch_bounds__(256) k_stage1(const float* __restrict__ x,
                                                const float* __restrict__ hk) {
    __shared__ float2 sm[64 * 32];
    const int s   = blockIdx.y;
    const int col = threadIdx.x & 31;
    const int a   = threadIdx.x >> 5;          // 0..7
    const int n2  = blockIdx.x * 32 + col;
    const float* xs = x  + (size_t)s * T_LEN;
    const float* hs = hk + (size_t)s * T_LEN;

    float2 v[8];
    #pragma unroll
    for (int b = 0; b < 4; b++) {
        int n = (a + 8*b) * N2 + n2;           // < 65536 always
        v[b] = make_float2(__bfloat162float(__float2bfloat16_rn(xs[n])), hs[n]);
    }
    // fft8 over b with upper half zero (t = z, s = z)
    {
        const float C = 0.70710678118654752440f;
        float2 t0=v[0], t1=v[1], t2=v[2], t3=v[3];
        float2 s0=v[0];
        float2 s1=cmul(v[1], make_float2(C,-C));
        float2 s2=mulnI(v[2]);
        float2 s3=cmul(v[3], make_float2(-C,-C));
        float2 a0=cadd(t0,t2), a1=csub(t0,t2), a2=cadd(t1,t3), a3=mulnI(csub(t1,t3));
        float2 b0=cadd(s0,s2), b1=csub(s0,s2), b2=cadd(s1,s3), b3=mulnI(csub(s1,s3));
        v[0]=cadd(a0,a2); v[4]=csub(a0,a2);
        v[2]=cadd(a1,a3); v[6]=csub(a1,a3);
        v[1]=cadd(b0,b2); v[5]=csub(b0,b2);
        v[3]=cadd(b1,b3); v[7]=csub(b1,b3);
    }
    // twiddle W_64^{a*j}
    {
        float2 W[8];
        twpow(W, twid(32, a));
        #pragma unroll
        for (int j = 1; j < 8; j++) v[j] = cmul(v[j], W[j]);
    }
    #pragma unroll
    for (int j = 0; j < 8; j++) sm[(j*8 + a)*32 + col] = v[j];
    __syncthreads();

    const int j = a;                            // phase-2 role
    #pragma unroll
    for (int q = 0; q < 8; q++) v[q] = sm[(j*8 + q)*32 + col];
    fft8<false>(v);                             // over a -> m ; k1 = j + 8m

    float2* zs = g_z + (size_t)s * NN;
    {
        float2 acc  = twid(NHALF, n2 * j);      // n2*j < 65536
        float2 step = twid(NHALF, 8 * n2);
        #pragma unroll
        for (int m = 0; m < 8; m++) {
            int k1 = j + 8*m;
            zs[k1 * N2 + n2] = cmul(v[m], acc);
            acc = cmul(acc, step);
        }
    }
}

// ---------------------------------------------------------------------------
// Stage 2 (512 threads, 2 blocks/SM): pair {g, 64-g} ({0,32} for g==0):
//   fwd radix-8,8,8 stages (both rows) -> FUSED S4+pointwise+IS4 in registers
//   (thread t takes row-A radix-4 group t and row-B group 511-t; complement
//   pairing is exactly group-aligned) -> inverse FFT row A only (realness:
//   u[64-k1] = conj(u[k1]) after conj inter-twiddle) -> store rows 0..32 as
//   fp16 with 1/N folded into the inter-twiddle.
// ---------------------------------------------------------------------------
__global__ void __launch_bounds__(512, 2) k_stage2() {
    __shared__ float2 smAB[2 * 2304];
    const int s = blockIdx.y;
    const int g = blockIdx.x;                   // 0..31
    const int rowA = g;
    const int rowB = (g == 0) ? 32 : 64 - g;
    const int tid = threadIdx.x;
    const int r = tid >> 8;                     // which row this thread serves
    const int u = tid & 255;
    const int myrow = r ? rowB : rowA;
    const bool invB = (g == 0);                 // does row B need the inverse path?
    float2* zs   = g_z + (size_t)s * NN;
    float2* glob = zs + myrow * N2;
    float2* sm   = smAB + r * 2304;
    float2* smA  = smAB;
    float2* smB  = smAB + 2304;

    float2 v[8], W[8];
    // S1: radix-8 over b (stride 256), twiddle W_2048^{u*j}
    #pragma unroll
    for (int b = 0; b < 8; b++) v[b] = glob[u + 256*b];
    fft8<false>(v);
    twpow(W, twid(1024, u));
    #pragma unroll
    for (int j = 1; j < 8; j++) v[j] = cmul(v[j], W[j]);
    #pragma unroll
    for (int j = 0; j < 8; j++) sm[PAD(j*256 + u)] = v[j];
    __syncthreads();

    // S2: radix-8 over d (stride 32), twiddle W_256^{c*j2}
    { const int j = u >> 5, c = u & 31, base = j*256 + c;
      #pragma unroll
      for (int d = 0; d < 8; d++) v[d] = sm[PAD(base + 32*d)];
      fft8<false>(v);
      twpow(W, twid(128, c));
      #pragma unroll
      for (int j2 = 1; j2 < 8; j2++) v[j2] = cmul(v[j2], W[j2]);
      #pragma unroll
      for (int j2 = 0; j2 < 8; j2++) sm[PAD(j*256 + j2*32 + c)] = v[j2];
    }
    __syncthreads();

    // S3: radix-8 over f (stride 4), twiddle W_32^{e*j3}
    { const int j = u >> 5, j2 = (u >> 2) & 7, e = u & 3, base = j*256 + j2*32 + e;
      #pragma unroll
      for (int f = 0; f < 8; f++) v[f] = sm[PAD(base + 4*f)];
      fft8<false>(v);
      twpow(W, twid(16, e));
      #pragma unroll
      for (int j3 = 1; j3 < 8; j3++) v[j3] = cmul(v[j3], W[j3]);
      #pragma unroll
      for (int j3 = 0; j3 < 8; j3++) sm[PAD(j*256 + j2*32 + j3*4 + e)] = v[j3];
    }
    __syncthreads();

    if (g != 0) {
        // FUSED S4 + pointwise + IS4 in registers. Thread tid owns row-A
        // radix-4 group tid and row-B group 511-tid. Complement of A element
        // 4*tid+e is element 3-e of B group 511-tid. Only smA group tid is
        // written (own-read-then-own-write; smB read-only) -> no extra sync.
        float2 a4[4], b4[4];
        #pragma unroll
        for (int e = 0; e < 4; e++) {
            a4[e] = smA[PAD(4*tid + e)];
            b4[e] = smB[PAD(4*(511 - tid) + e)];
        }
        fft4<false>(a4);
        fft4<false>(b4);
        float2 ya[4];
        #pragma unroll
        for (int e = 0; e < 4; e++) ya[e] = pw(a4[e], b4[3-e]);
        fft4<true>(ya);
        #pragma unroll
        for (int e = 0; e < 4; e++) smA[PAD(4*tid + e)] = ya[e];
    } else {
        // g==0: S4 both rows (stored), explicit pairing, IS4 both rows.
        #pragma unroll
        for (int gi = 0; gi < 2; gi++) {
            const int grp = u + 256*gi;
            float2 w4[4];
            #pragma unroll
            for (int e = 0; e < 4; e++) w4[e] = sm[PAD(4*grp + e)];
            fft4<false>(w4);
            #pragma unroll
            for (int m = 0; m < 4; m++) sm[PAD(4*grp + m)] = w4[m];
        }
        __syncthreads();
        // row 0 pairs with itself at k2' = (2048-k2) mod 2048 (k2-space);
        // row 32 self-pairs position-locally.
        if (tid < 256) {
            #pragma unroll
            for (int e = 0; e < 4; e++) {
                int k2 = 4*tid + e;
                int pa = POS(k2);
                int pb = POS((2048 - k2) & 2047);
                float2 Za = smA[PAD(pa)];
                float2 Zb = smA[PAD(pb)];
                float2 Y = pw(Za, Zb);
                smA[PAD(pa)] = Y;
                smA[PAD(pb)] = cconj(Y);
            }
            if (tid == 0) {                      // k2 = 1024 self-pair, pos = 2
                float2 Za = smA[PAD(2)];
                smA[PAD(2)] = pw(Za, Za);
            }
        } else {
            const int u2 = tid - 256;
            #pragma unroll
            for (int e = 0; e < 4; e++) {
                int p = 4*u2 + e;
                float2 Za = smB[PAD(p)];
                float2 Zb = smB[PAD(2047 - p)];
                float2 Y = pw(Za, Zb);
                smB[PAD(p)]        = Y;
                smB[PAD(2047 - p)] = cconj(Y);
            }
        }
        __syncthreads();
        // IS4 (both rows)
        #pragma unroll
        for (int gi = 0; gi < 2; gi++) {
            const int grp = u + 256*gi;
            float2 w4[4];
            #pragma unroll
            for (int e = 0; e < 4; e++) w4[e] = sm[PAD(4*grp + e)];
            fft4<true>(w4);
            #pragma unroll
            for (int e = 0; e < 4; e++) sm[PAD(4*grp + e)] = w4[e];
        }
    }
    __syncthreads();

    // IS3: conj twiddle W_32^{-e*j3}, inverse radix-8 over j3 -> f
    if (r == 0 || invB) {
      const int j = u >> 5, j2 = (u >> 2) & 7, e = u & 3, base = j*256 + j2*32 + e;
      #pragma unroll
      for (int j3 = 0; j3 < 8; j3++) v[j3] = sm[PAD(base + 4*j3)];
      twpow(W, twidc(16, e));
      #pragma unroll
      for (int j3 = 1; j3 < 8; j3++) v[j3] = cmul(v[j3], W[j3]);
      fft8<true>(v);
      #pragma unroll
      for (int f = 0; f < 8; f++) sm[PAD(base + 4*f)] = v[f];
    }
    __syncthreads();

    // IS2: conj twiddle W_256^{-c*j2}, inverse radix-8 over j2 -> d
    if (r == 0 || invB) {
      const int j = u >> 5, c = u & 31, base = j*256 + c;
      #pragma unroll
      for (int j2 = 0; j2 < 8; j2++) v[j2] = sm[PAD(base + 32*j2)];
      twpow(W, twidc(128, c));
      #pragma unroll
      for (int j2 = 1; j2 < 8; j2++) v[j2] = cmul(v[j2], W[j2]);
      fft8<true>(v);
      #pragma unroll
      for (int d = 0; d < 8; d++) sm[PAD(base + 32*d)] = v[d];
    }
    __syncthreads();

    // IS1: conj twiddle W_2048^{-a*j}, inverse radix-8 over j -> b,
    // conj inter-step twiddle W_N^{-row*(b*256+a)} with 1/N folded in,
    // store as fp16 (rows <= 32 only).
    if (r == 0 || invB) {
      const int a = u;
      #pragma unroll
      for (int j = 0; j < 8; j++) v[j] = sm[PAD(j*256 + a)];
      twpow(W, twidc(1024, a));
      #pragma unroll
      for (int j = 1; j < 8; j++) v[j] = cmul(v[j], W[j]);
      fft8<true>(v);
      const float SC = 1.0f / (float)NN;
      float2 acc  = twidc(NHALF, myrow * a);
      acc.x *= SC; acc.y *= SC;                 // scale survives the chain
      float2 step = twidc(NHALF, 256 * myrow);
      __half2* gh = g_h + (size_t)s * (33 * N2) + myrow * N2;
      #pragma unroll
      for (int b = 0; b < 8; b++) {
          float2 y = cmul(v[b], acc);
          gh[b*256 + a] = __floats2half2_rn(y.x, y.y);
          acc = cmul(acc, step);
      }
    }
}

// ---------------------------------------------------------------------------
// Stage 3: inverse 64-pt FFT along k1 (two register radix-8 passes, one smem
// exchange), write real part of n1 < 32 only (1/N already folded in stage 2).
// Rows 33..63 reconstructed as conj(row 64-r); reads fp16.
// ---------------------------------------------------------------------------
__global__ void __launch_bounds__(256) k_stage3(float* __restrict__ out) {
    __shared__ float2 sm[64 * 32];
    const int s   = blockIdx.y;
    const int col = threadIdx.x & 31;
    const int j   = threadIdx.x >> 5;
    const int n2  = blockIdx.x * 32 + col;
    const __half2* gh = g_h + (size_t)s * (33 * N2);

    float2 v[8];
    #pragma unroll
    for (int m = 0; m < 8; m++) {
        int rr = j + 8*m;
        if (rr <= 32) {
            v[m] = __half22float2(gh[rr * N2 + n2]);
        } else {
            float2 t = __half22float2(gh[(64 - rr) * N2 + n2]);
            v[m] = make_float2(t.x, -t.y);
        }
    }
    fft8<true>(v);                               // over m -> a
    #pragma unroll
    for (int a = 0; a < 8; a++) sm[(a*8 + j)*32 + col] = v[a];
    __syncthreads();

    const int a = threadIdx.x >> 5;
    #pragma unroll
    for (int q = 0; q < 8; q++) v[q] = sm[(a*8 + q)*32 + col];
    { float2 W[8];
      twpow(W, twidc(32, a));
      #pragma unroll
      for (int q = 1; q < 8; q++) v[q] = cmul(v[q], W[q]);
    }
    fft8<true>(v);                               // over j -> b ; n1 = a + 8b

    float* os = out + (size_t)s * T_LEN;
    #pragma unroll
    for (int b = 0; b < 4; b++)
        os[(a + 8*b) * N2 + n2] = v[b].x;
}

extern "C" void kernel_launch(void* const* d_in, const int* in_sizes, int n_in,
                              void* d_out, int out_size) {
    const float* x = (const float*)d_in[0];
    const float* h = (const float*)d_in[1];
    float* out = (float*)d_out;

    k_init_tw<<<NN / 256, 256>>>();
    k_stage1<<<dim3(N2 / 32, SEQ), 256>>>(x, h);
    k_stage2<<<dim3(32, SEQ), 512>>>();
    k_stage3<<<dim3(N2 / 32, SEQ), 256>>>(out);
}

// round 10
// speedup vs baseline: 2.1021x; 1.0613x over previous
#include <cuda_runtime.h>
#include <cuda_bf16.h>
#include <cuda_fp16.h>

#define SEQ   512
#define T_LEN 65536
#define NN    131072
#define NHALF 65536
#define N2    2048

// Scratch (device globals; no allocations allowed)
__device__ __half2 g_zh[(size_t)SEQ * NN];      // 256 MiB fp16 stage1->2 buffer
__device__ __half2 g_h[(size_t)SEQ * 33 * N2];  // 138 MiB fp16 stage2->3 buffer
__device__ float2 g_tw[NN];                     // g_tw[h+p] = exp(-i*pi*p/h)

static __device__ __forceinline__ float2 cmul(float2 a, float2 b) {
    return make_float2(fmaf(a.x, b.x, -a.y * b.y), fmaf(a.x, b.y, a.y * b.x));
}
static __device__ __forceinline__ float2 cadd(float2 a, float2 b) { return make_float2(a.x+b.x, a.y+b.y); }
static __device__ __forceinline__ float2 csub(float2 a, float2 b) { return make_float2(a.x-b.x, a.y-b.y); }
static __device__ __forceinline__ float2 mulnI(float2 a) { return make_float2(a.y, -a.x); }   // * (-i)
static __device__ __forceinline__ float2 mulpI(float2 a) { return make_float2(-a.y, a.x); }   // * (+i)
static __device__ __forceinline__ float2 cconj(float2 a) { return make_float2(a.x, -a.y); }

// W_{2*Mhalf}^q  for q in [0, 2*Mhalf)
static __device__ __forceinline__ float2 twid(int Mhalf, int q) {
    if (q < Mhalf) return g_tw[Mhalf + q];
    float2 t = g_tw[q];                    // == g_tw[Mhalf + (q - Mhalf)]
    return make_float2(-t.x, -t.y);
}
// conj(W_{2*Mhalf}^q)
static __device__ __forceinline__ float2 twidc(int Mhalf, int q) {
    if (q < Mhalf) { float2 t = g_tw[Mhalf + q]; return make_float2(t.x, -t.y); }
    float2 t = g_tw[q];
    return make_float2(-t.x, t.y);
}

// Powers W[j] = w^j, j=1..7, built with a depth-3 tree (6 cmuls, 1 load).
static __device__ __forceinline__ void twpow(float2 W[8], float2 w) {
    W[1] = w;
    W[2] = cmul(w, w);
    W[3] = cmul(W[2], w);
    W[4] = cmul(W[2], W[2]);
    W[5] = cmul(W[2], W[3]);
    W[6] = cmul(W[3], W[3]);
    W[7] = cmul(W[3], W[4]);
}

// 8-pt DFT, natural in/out. INV => conjugated twiddles (unnormalized inverse).
template<bool INV>
static __device__ __forceinline__ void fft8(float2 z[8]) {
    const float C = 0.70710678118654752440f;
    float2 t0=cadd(z[0],z[4]), t1=cadd(z[1],z[5]), t2=cadd(z[2],z[6]), t3=cadd(z[3],z[7]);
    float2 s0=csub(z[0],z[4]), s1=csub(z[1],z[5]), s2=csub(z[2],z[6]), s3=csub(z[3],z[7]);
    if (!INV) {
        s1 = cmul(s1, make_float2(C,-C)); s2 = mulnI(s2); s3 = cmul(s3, make_float2(-C,-C));
    } else {
        s1 = cmul(s1, make_float2(C, C)); s2 = mulpI(s2); s3 = cmul(s3, make_float2(-C, C));
    }
    float2 a0=cadd(t0,t2), a1=csub(t0,t2), a2=cadd(t1,t3), a3=csub(t1,t3);
    a3 = INV ? mulpI(a3) : mulnI(a3);
    float2 b0=cadd(s0,s2), b1=csub(s0,s2), b2=cadd(s1,s3), b3=csub(s1,s3);
    b3 = INV ? mulpI(b3) : mulnI(b3);
    z[0]=cadd(a0,a2); z[4]=csub(a0,a2);
    z[2]=cadd(a1,a3); z[6]=csub(a1,a3);
    z[1]=cadd(b0,b2); z[5]=csub(b0,b2);
    z[3]=cadd(b1,b3); z[7]=csub(b1,b3);
}

template<bool INV>
static __device__ __forceinline__ void fft4(float2 z[4]) {
    float2 a0=cadd(z[0],z[2]), a1=csub(z[0],z[2]);
    float2 a2=cadd(z[1],z[3]), a3=csub(z[1],z[3]);
    a3 = INV ? mulpI(a3) : mulnI(a3);
    z[0]=cadd(a0,a2); z[2]=csub(a0,a2);
    z[1]=cadd(a1,a3); z[3]=csub(a1,a3);
}

// Hermitian unpack + pointwise: Za = Z[k], Zb = Z[N-k]; returns Y[k] = X[k]*H[k]
static __device__ __forceinline__ float2 pw(float2 Za, float2 Zb) {
    float2 X = make_float2(0.5f*(Za.x+Zb.x),  0.5f*(Za.y-Zb.y));
    float2 H = make_float2(0.5f*(Za.y+Zb.y), -0.5f*(Za.x-Zb.x));
    return cmul(X, H);
}

#define PAD(p) ((p) + (((p) >> 5) << 2))
#define POS(k2) ((((k2)&7)<<8) + ((((k2)>>3)&7)<<5) + ((((k2)>>6)&7)<<2) + ((k2)>>9))

__global__ void k_init_tw() {
    int idx = blockIdx.x * blockDim.x + threadIdx.x;
    if (idx >= NN) return;
    if (idx == 0) { g_tw[0] = make_float2(1.0f, 0.0f); return; }
    int h = 1 << (31 - __clz(idx));
    int p = idx - h;
    float s, c;
    sincospif(-(float)p / (float)h, &s, &c);
    g_tw[idx] = make_float2(c, s);
}

// ---------------------------------------------------------------------------
// Stage 1: pack z = bf16(x) + i*h (rows n1>=32 are zero) + 64-pt FFT along n1
// (two register radix-8 passes, one smem exchange) + twiddle W_N^{k1*n2}.
// Output (fp16): g_zh[s][k1*2048 + n2]
// ---------------------------------------------------------------------------
__global__ void __launch_bounds__(256) k_stage1(const float* __restrict__ x,
                                                const float* __restrict__ hk) {
    __shared__ float2 sm[64 * 32];
    const int s   = blockIdx.y;
    const int col = threadIdx.x & 31;
    const int a   = threadIdx.x >> 5;          // 0..7
    const int n2  = blockIdx.x * 32 + col;
    const float* xs = x  + (size_t)s * T_LEN;
    const float* hs = hk + (size_t)s * T_LEN;

    float2 v[8];
    #pragma unroll
    for (int b = 0; b < 4; b++) {
        int n = (a + 8*b) * N2 + n2;           // < 65536 always
        v[b] = make_float2(__bfloat162float(__float2bfloat16_rn(xs[n])), hs[n]);
    }
    // fft8 over b with upper half zero (t = z, s = z)
    {
        const float C = 0.70710678118654752440f;
        float2 t0=v[0], t1=v[1], t2=v[2], t3=v[3];
        float2 s0=v[0];
        float2 s1=cmul(v[1], make_float2(C,-C));
        float2 s2=mulnI(v[2]);
        float2 s3=cmul(v[3], make_float2(-C,-C));
        float2 a0=cadd(t0,t2), a1=csub(t0,t2), a2=cadd(t1,t3), a3=mulnI(csub(t1,t3));
        float2 b0=cadd(s0,s2), b1=csub(s0,s2), b2=cadd(s1,s3), b3=mulnI(csub(s1,s3));
        v[0]=cadd(a0,a2); v[4]=csub(a0,a2);
        v[2]=cadd(a1,a3); v[6]=csub(a1,a3);
        v[1]=cadd(b0,b2); v[5]=csub(b0,b2);
        v[3]=cadd(b1,b3); v[7]=csub(b1,b3);
    }
    // twiddle W_64^{a*j}
    {
        float2 W[8];
        twpow(W, twid(32, a));
        #pragma unroll
        for (int j = 1; j < 8; j++) v[j] = cmul(v[j], W[j]);
    }
    #pragma unroll
    for (int j = 0; j < 8; j++) sm[(j*8 + a)*32 + col] = v[j];
    __syncthreads();

    const int j = a;                            // phase-2 role
    #pragma unroll
    for (int q = 0; q < 8; q++) v[q] = sm[(j*8 + q)*32 + col];
    fft8<false>(v);                             // over a -> m ; k1 = j + 8m

    __half2* zs = g_zh + (size_t)s * NN;
    {
        float2 acc  = twid(NHALF, n2 * j);      // n2*j < 65536
        float2 step = twid(NHALF, 8 * n2);
        #pragma unroll
        for (int m = 0; m < 8; m++) {
            int k1 = j + 8*m;
            float2 y = cmul(v[m], acc);
            zs[k1 * N2 + n2] = __floats2half2_rn(y.x, y.y);
            acc = cmul(acc, step);
        }
    }
}

// ---------------------------------------------------------------------------
// Stage 2 (512 threads, 2 blocks/SM): pair {g, 64-g} ({0,32} for g==0):
//   fwd radix-8,8,8 stages (both rows, fp16 in) -> FUSED S4+pointwise+IS4 in
//   registers (thread t: row-A group t, row-B group 511-t; complement pairing
//   is group-aligned) -> inverse FFT row A only (realness: u[64-k1] =
//   conj(u[k1]) after conj inter-twiddle) -> store rows 0..32 as fp16 with
//   1/N folded into the inter-twiddle.
// ---------------------------------------------------------------------------
__global__ void __launch_bounds__(512, 2) k_stage2() {
    __shared__ float2 smAB[2 * 2304];
    const int s = blockIdx.y;
    const int g = blockIdx.x;                   // 0..31
    const int rowA = g;
    const int rowB = (g == 0) ? 32 : 64 - g;
    const int tid = threadIdx.x;
    const int r = tid >> 8;                     // which row this thread serves
    const int u = tid & 255;
    const int myrow = r ? rowB : rowA;
    const bool invB = (g == 0);                 // does row B need the inverse path?
    const __half2* glob = g_zh + (size_t)s * NN + myrow * N2;
    float2* sm   = smAB + r * 2304;
    float2* smA  = smAB;
    float2* smB  = smAB + 2304;

    float2 v[8], W[8];
    // S1: radix-8 over b (stride 256), twiddle W_2048^{u*j}
    #pragma unroll
    for (int b = 0; b < 8; b++) v[b] = __half22float2(glob[u + 256*b]);
    fft8<false>(v);
    twpow(W, twid(1024, u));
    #pragma unroll
    for (int j = 1; j < 8; j++) v[j] = cmul(v[j], W[j]);
    #pragma unroll
    for (int j = 0; j < 8; j++) sm[PAD(j*256 + u)] = v[j];
    __syncthreads();

    // S2: radix-8 over d (stride 32), twiddle W_256^{c*j2}
    { const int j = u >> 5, c = u & 31, base = j*256 + c;
      #pragma unroll
      for (int d = 0; d < 8; d++) v[d] = sm[PAD(base + 32*d)];
      fft8<false>(v);
      twpow(W, twid(128, c));
      #pragma unroll
      for (int j2 = 1; j2 < 8; j2++) v[j2] = cmul(v[j2], W[j2]);
      #pragma unroll
      for (int j2 = 0; j2 < 8; j2++) sm[PAD(j*256 + j2*32 + c)] = v[j2];
    }
    __syncthreads();

    // S3: radix-8 over f (stride 4), twiddle W_32^{e*j3}
    { const int j = u >> 5, j2 = (u >> 2) & 7, e = u & 3, base = j*256 + j2*32 + e;
      #pragma unroll
      for (int f = 0; f < 8; f++) v[f] = sm[PAD(base + 4*f)];
      fft8<false>(v);
      twpow(W, twid(16, e));
      #pragma unroll
      for (int j3 = 1; j3 < 8; j3++) v[j3] = cmul(v[j3], W[j3]);
      #pragma unroll
      for (int j3 = 0; j3 < 8; j3++) sm[PAD(j*256 + j2*32 + j3*4 + e)] = v[j3];
    }
    __syncthreads();

    if (g != 0) {
        // FUSED S4 + pointwise + IS4 in registers. Thread tid owns row-A
        // radix-4 group tid and row-B group 511-tid. Complement of A element
        // 4*tid+e is element 3-e of B group 511-tid. Only smA group tid is
        // written (own-read-then-own-write; smB read-only) -> no extra sync.
        float2 a4[4], b4[4];
        #pragma unroll
        for (int e = 0; e < 4; e++) {
            a4[e] = smA[PAD(4*tid + e)];
            b4[e] = smB[PAD(4*(511 - tid) + e)];
        }
        fft4<false>(a4);
        fft4<false>(b4);
        float2 ya[4];
        #pragma unroll
        for (int e = 0; e < 4; e++) ya[e] = pw(a4[e], b4[3-e]);
        fft4<true>(ya);
        #pragma unroll
        for (int e = 0; e < 4; e++) smA[PAD(4*tid + e)] = ya[e];
    } else {
        // g==0: S4 both rows (stored), explicit pairing, IS4 both rows.
        #pragma unroll
        for (int gi = 0; gi < 2; gi++) {
            const int grp = u + 256*gi;
            float2 w4[4];
            #pragma unroll
            for (int e = 0; e < 4; e++) w4[e] = sm[PAD(4*grp + e)];
            fft4<false>(w4);
            #pragma unroll
            for (int m = 0; m < 4; m++) sm[PAD(4*grp + m)] = w4[m];
        }
        __syncthreads();
        // row 0 pairs with itself at k2' = (2048-k2) mod 2048 (k2-space);
        // row 32 self-pairs position-locally.
        if (tid < 256) {
            #pragma unroll
            for (int e = 0; e < 4; e++) {
                int k2 = 4*tid + e;
                int pa = POS(k2);
                int pb = POS((2048 - k2) & 2047);
                float2 Za = smA[PAD(pa)];
                float2 Zb = smA[PAD(pb)];
                float2 Y = pw(Za, Zb);
                smA[PAD(pa)] = Y;
                smA[PAD(pb)] = cconj(Y);
            }
            if (tid == 0) {                      // k2 = 1024 self-pair, pos = 2
                float2 Za = smA[PAD(2)];
                smA[PAD(2)] = pw(Za, Za);
            }
        } else {
            const int u2 = tid - 256;
            #pragma unroll
            for (int e = 0; e < 4; e++) {
                int p = 4*u2 + e;
                float2 Za = smB[PAD(p)];
                float2 Zb = smB[PAD(2047 - p)];
                float2 Y = pw(Za, Zb);
                smB[PAD(p)]        = Y;
                smB[PAD(2047 - p)] = cconj(Y);
            }
        }
        __syncthreads();
        // IS4 (both rows)
        #pragma unroll
        for (int gi = 0; gi < 2; gi++) {
            const int grp = u + 256*gi;
            float2 w4[4];
            #pragma unroll
            for (int e = 0; e < 4; e++) w4[e] = sm[PAD(4*grp + e)];
            fft4<true>(w4);
            #pragma unroll
            for (int e = 0; e < 4; e++) sm[PAD(4*grp + e)] = w4[e];
        }
    }
    __syncthreads();

    // IS3: conj twiddle W_32^{-e*j3}, inverse radix-8 over j3 -> f
    if (r == 0 || invB) {
      const int j = u >> 5, j2 = (u >> 2) & 7, e = u & 3, base = j*256 + j2*32 + e;
      #pragma unroll
      for (int j3 = 0; j3 < 8; j3++) v[j3] = sm[PAD(base + 4*j3)];
      twpow(W, twidc(16, e));
      #pragma unroll
      for (int j3 = 1; j3 < 8; j3++) v[j3] = cmul(v[j3], W[j3]);
      fft8<true>(v);
      #pragma unroll
      for (int f = 0; f < 8; f++) sm[PAD(base + 4*f)] = v[f];
    }
    __syncthreads();

    // IS2: conj twiddle W_256^{-c*j2}, inverse radix-8 over j2 -> d
    if (r == 0 || invB) {
      const int j = u >> 5, c = u & 31, base = j*256 + c;
      #pragma unroll
      for (int j2 = 0; j2 < 8; j2++) v[j2] = sm[PAD(base + 32*j2)];
      twpow(W, twidc(128, c));
      #pragma unroll
      for (int j2 = 1; j2 < 8; j2++) v[j2] = cmul(v[j2], W[j2]);
      fft8<true>(v);
      #pragma unroll
      for (int d = 0; d < 8; d++) sm[PAD(base + 32*d)] = v[d];
    }
    __syncthreads();

    // IS1: conj twiddle W_2048^{-a*j}, inverse radix-8 over j -> b,
    // conj inter-step twiddle W_N^{-row*(b*256+a)} with 1/N folded in,
    // store as fp16 (rows <= 32 only).
    if (r == 0 || invB) {
      const int a = u;
      #pragma unroll
      for (int j = 0; j < 8; j++) v[j] = sm[PAD(j*256 + a)];
      twpow(W, twidc(1024, a));
      #pragma unroll
      for (int j = 1; j < 8; j++) v[j] = cmul(v[j], W[j]);
      fft8<true>(v);
      const float SC = 1.0f / (float)NN;
      float2 acc  = twidc(NHALF, myrow * a);
      acc.x *= SC; acc.y *= SC;                 // scale survives the chain
      float2 step = twidc(NHALF, 256 * myrow);
      __half2* gh = g_h + (size_t)s * (33 * N2) + myrow * N2;
      #pragma unroll
      for (int b = 0; b < 8; b++) {
          float2 y = cmul(v[b], acc);
          gh[b*256 + a] = __floats2half2_rn(y.x, y.y);
          acc = cmul(acc, step);
      }
    }
}

// ---------------------------------------------------------------------------
// Stage 3: inverse 64-pt FFT along k1 (two register radix-8 passes, one smem
// exchange), write real part of n1 < 32 only (1/N already folded in stage 2).
// Rows 33..63 reconstructed as conj(row 64-r); reads fp16.
// ---------------------------------------------------------------------------
__global__ void __launch_bounds__(256) k_stage3(float* __restrict__ out) {
    __shared__ float2 sm[64 * 32];
    const int s   = blockIdx.y;
    const int col = threadIdx.x & 31;
    const int j   = threadIdx.x >> 5;
    const int n2  = blockIdx.x * 32 + col;
    const __half2* gh = g_h + (size_t)s * (33 * N2);

    float2 v[8];
    #pragma unroll
    for (int m = 0; m < 8; m++) {
        int rr = j + 8*m;
        if (rr <= 32) {
            v[m] = __half22float2(gh[rr * N2 + n2]);
        } else {
            float2 t = __half22float2(gh[(64 - rr) * N2 + n2]);
            v[m] = make_float2(t.x, -t.y);
        }
    }
    fft8<true>(v);                               // over m -> a
    #pragma unroll
    for (int a = 0; a < 8; a++) sm[(a*8 + j)*32 + col] = v[a];
    __syncthreads();

    const int a = threadIdx.x >> 5;
    #pragma unroll
    for (int q = 0; q < 8; q++) v[q] = sm[(a*8 + q)*32 + col];
    { float2 W[8];
      twpow(W, twidc(32, a));
      #pragma unroll
      for (int q = 1; q < 8; q++) v[q] = cmul(v[q], W[q]);
    }
    fft8<true>(v);                               // over j -> b ; n1 = a + 8b

    float* os = out + (size_t)s * T_LEN;
    #pragma unroll
    for (int b = 0; b < 4; b++)
        os[(a + 8*b) * N2 + n2] = v[b].x;
}

extern "C" void kernel_launch(void* const* d_in, const int* in_sizes, int n_in,
                              void* d_out, int out_size) {
    const float* x = (const float*)d_in[0];
    const float* h = (const float*)d_in[1];
    float* out = (float*)d_out;

    k_init_tw<<<NN / 256, 256>>>();
    k_stage1<<<dim3(N2 / 32, SEQ), 256>>>(x, h);
    k_stage2<<<dim3(32, SEQ), 512>>>();
    k_stage3<<<dim3(N2 / 32, SEQ), 256>>>(out);
}

// round 11
// speedup vs baseline: 2.3056x; 1.0968x over previous
#include <cuda_runtime.h>
#include <cuda_bf16.h>
#include <cuda_fp16.h>

#define SEQ   512
#define T_LEN 65536
#define NN    131072
#define NHALF 65536
#define N2    2048

// Scratch (device globals; no allocations allowed)
__device__ __half2 g_zh[(size_t)SEQ * NN];      // 256 MiB fp16 stage1->2 buffer
__device__ __half2 g_h[(size_t)SEQ * 33 * N2];  // 138 MiB fp16 stage2->3 buffer
__device__ float2 g_tw[NN];                     // g_tw[h+p] = exp(-i*pi*p/h)

static __device__ __forceinline__ float2 cmul(float2 a, float2 b) {
    return make_float2(fmaf(a.x, b.x, -a.y * b.y), fmaf(a.x, b.y, a.y * b.x));
}
static __device__ __forceinline__ float2 cadd(float2 a, float2 b) { return make_float2(a.x+b.x, a.y+b.y); }
static __device__ __forceinline__ float2 csub(float2 a, float2 b) { return make_float2(a.x-b.x, a.y-b.y); }
static __device__ __forceinline__ float2 mulnI(float2 a) { return make_float2(a.y, -a.x); }   // * (-i)
static __device__ __forceinline__ float2 mulpI(float2 a) { return make_float2(-a.y, a.x); }   // * (+i)
static __device__ __forceinline__ float2 cconj(float2 a) { return make_float2(a.x, -a.y); }

// W_{2*Mhalf}^q  for q in [0, 2*Mhalf)
static __device__ __forceinline__ float2 twid(int Mhalf, int q) {
    if (q < Mhalf) return g_tw[Mhalf + q];
    float2 t = g_tw[q];                    // == g_tw[Mhalf + (q - Mhalf)]
    return make_float2(-t.x, -t.y);
}
// conj(W_{2*Mhalf}^q)
static __device__ __forceinline__ float2 twidc(int Mhalf, int q) {
    if (q < Mhalf) { float2 t = g_tw[Mhalf + q]; return make_float2(t.x, -t.y); }
    float2 t = g_tw[q];
    return make_float2(-t.x, t.y);
}

// Powers W[j] = w^j, j=1..7, built with a depth-3 tree (6 cmuls, 1 load).
static __device__ __forceinline__ void twpow(float2 W[8], float2 w) {
    W[1] = w;
    W[2] = cmul(w, w);
    W[3] = cmul(W[2], w);
    W[4] = cmul(W[2], W[2]);
    W[5] = cmul(W[2], W[3]);
    W[6] = cmul(W[3], W[3]);
    W[7] = cmul(W[3], W[4]);
}

// 8-pt DFT, natural in/out. INV => conjugated twiddles (unnormalized inverse).
template<bool INV>
static __device__ __forceinline__ void fft8(float2 z[8]) {
    const float C = 0.70710678118654752440f;
    float2 t0=cadd(z[0],z[4]), t1=cadd(z[1],z[5]), t2=cadd(z[2],z[6]), t3=cadd(z[3],z[7]);
    float2 s0=csub(z[0],z[4]), s1=csub(z[1],z[5]), s2=csub(z[2],z[6]), s3=csub(z[3],z[7]);
    if (!INV) {
        s1 = cmul(s1, make_float2(C,-C)); s2 = mulnI(s2); s3 = cmul(s3, make_float2(-C,-C));
    } else {
        s1 = cmul(s1, make_float2(C, C)); s2 = mulpI(s2); s3 = cmul(s3, make_float2(-C, C));
    }
    float2 a0=cadd(t0,t2), a1=csub(t0,t2), a2=cadd(t1,t3), a3=csub(t1,t3);
    a3 = INV ? mulpI(a3) : mulnI(a3);
    float2 b0=cadd(s0,s2), b1=csub(s0,s2), b2=cadd(s1,s3), b3=csub(s1,s3);
    b3 = INV ? mulpI(b3) : mulnI(b3);
    z[0]=cadd(a0,a2); z[4]=csub(a0,a2);
    z[2]=cadd(a1,a3); z[6]=csub(a1,a3);
    z[1]=cadd(b0,b2); z[5]=csub(b0,b2);
    z[3]=cadd(b1,b3); z[7]=csub(b1,b3);
}

template<bool INV>
static __device__ __forceinline__ void fft4(float2 z[4]) {
    float2 a0=cadd(z[0],z[2]), a1=csub(z[0],z[2]);
    float2 a2=cadd(z[1],z[3]), a3=csub(z[1],z[3]);
    a3 = INV ? mulpI(a3) : mulnI(a3);
    z[0]=cadd(a0,a2); z[2]=csub(a0,a2);
    z[1]=cadd(a1,a3); z[3]=csub(a1,a3);
}

// Hermitian unpack + pointwise: Za = Z[k], Zb = Z[N-k]; returns Y[k] = X[k]*H[k]
static __device__ __forceinline__ float2 pw(float2 Za, float2 Zb) {
    float2 X = make_float2(0.5f*(Za.x+Zb.x),  0.5f*(Za.y-Zb.y));
    float2 H = make_float2(0.5f*(Za.y+Zb.y), -0.5f*(Za.x-Zb.x));
    return cmul(X, H);
}

#define PAD(p) ((p) + (((p) >> 5) << 2))
#define POS(k2) ((((k2)&7)<<8) + ((((k2)>>3)&7)<<5) + ((((k2)>>6)&7)<<2) + ((k2)>>9))

__global__ void k_init_tw() {
    int idx = blockIdx.x * blockDim.x + threadIdx.x;
    if (idx >= NN) return;
    if (idx == 0) { g_tw[0] = make_float2(1.0f, 0.0f); return; }
    int h = 1 << (31 - __clz(idx));
    int p = idx - h;
    float s, c;
    sincospif(-(float)p / (float)h, &s, &c);
    g_tw[idx] = make_float2(c, s);
}

// ---------------------------------------------------------------------------
// Stage 1: pack z = bf16(x) + i*h (rows n1>=32 are zero) + 64-pt FFT along n1
// (two register radix-8 passes, one smem exchange) + twiddle W_N^{k1*n2}.
// Output (fp16): g_zh[s][k1*2048 + n2]
// ---------------------------------------------------------------------------
__global__ void __launch_bounds__(256) k_stage1(const float* __restrict__ x,
                                                const float* __restrict__ hk) {
    __shared__ float2 sm[64 * 32];
    const int s   = blockIdx.y;
    const int col = threadIdx.x & 31;
    const int a   = threadIdx.x >> 5;          // 0..7
    const int n2  = blockIdx.x * 32 + col;
    const float* xs = x  + (size_t)s * T_LEN;
    const float* hs = hk + (size_t)s * T_LEN;

    float2 v[8];
    #pragma unroll
    for (int b = 0; b < 4; b++) {
        int n = (a + 8*b) * N2 + n2;           // < 65536 always
        v[b] = make_float2(__bfloat162float(__float2bfloat16_rn(xs[n])), hs[n]);
    }
    // fft8 over b with upper half zero (t = z, s = z)
    {
        const float C = 0.70710678118654752440f;
        float2 t0=v[0], t1=v[1], t2=v[2], t3=v[3];
        float2 s0=v[0];
        float2 s1=cmul(v[1], make_float2(C,-C));
        float2 s2=mulnI(v[2]);
        float2 s3=cmul(v[3], make_float2(-C,-C));
        float2 a0=cadd(t0,t2), a1=csub(t0,t2), a2=cadd(t1,t3), a3=mulnI(csub(t1,t3));
        float2 b0=cadd(s0,s2), b1=csub(s0,s2), b2=cadd(s1,s3), b3=mulnI(csub(s1,s3));
        v[0]=cadd(a0,a2); v[4]=csub(a0,a2);
        v[2]=cadd(a1,a3); v[6]=csub(a1,a3);
        v[1]=cadd(b0,b2); v[5]=csub(b0,b2);
        v[3]=cadd(b1,b3); v[7]=csub(b1,b3);
    }
    // twiddle W_64^{a*j}
    {
        float2 W[8];
        twpow(W, twid(32, a));
        #pragma unroll
        for (int j = 1; j < 8; j++) v[j] = cmul(v[j], W[j]);
    }
    #pragma unroll
    for (int j = 0; j < 8; j++) sm[(j*8 + a)*32 + col] = v[j];
    __syncthreads();

    const int j = a;                            // phase-2 role
    #pragma unroll
    for (int q = 0; q < 8; q++) v[q] = sm[(j*8 + q)*32 + col];
    fft8<false>(v);                             // over a -> m ; k1 = j + 8m

    __half2* zs = g_zh + (size_t)s * NN;
    {
        float2 acc  = twid(NHALF, n2 * j);      // n2*j < 65536
        float2 step = twid(NHALF, 8 * n2);
        #pragma unroll
        for (int m = 0; m < 8; m++) {
            int k1 = j + 8*m;
            float2 y = cmul(v[m], acc);
            zs[k1 * N2 + n2] = __floats2half2_rn(y.x, y.y);
            acc = cmul(acc, step);
        }
    }
}

// ---------------------------------------------------------------------------
// Stage 2 (256 threads, 4 blocks/SM, ZERO idle): pair {g, 64-g} ({0,32} g==0).
// Rows processed SEQUENTIALLY inside each stage (one barrier per stage, same
// count as before); per-stage twiddle power-trees computed once, reused for
// both rows. Forward: 2 rows/thread-group; inverse: row A only (realness:
// u[64-k1] = conj(u[k1]) after conj inter-twiddle) — now with ALL threads
// busy. g==0 inverts rows 0 and 32 (nInv=2). Stores rows 0..32 as fp16 with
// 1/N folded into the inter-twiddle.
// ---------------------------------------------------------------------------
__global__ void __launch_bounds__(256, 4) k_stage2() {
    __shared__ float2 smA[2304];
    __shared__ float2 smB[2304];
    const int s = blockIdx.y;
    const int g = blockIdx.x;                   // 0..31
    const int rowA = g;
    const int rowB = (g == 0) ? 32 : 64 - g;
    const int u = threadIdx.x;                  // 0..255
    const int nInv = (g == 0) ? 2 : 1;
    const __half2* zb = g_zh + (size_t)s * NN;

    float2 v[8], W[8];

    // S1: radix-8 over stride 256, twiddle W_2048^{u*j} (shared by both rows)
    twpow(W, twid(1024, u));
    #pragma unroll
    for (int rr = 0; rr < 2; rr++) {
        const __half2* glob = zb + (rr ? rowB : rowA) * N2;
        float2* sm = rr ? smB : smA;
        #pragma unroll
        for (int b = 0; b < 8; b++) v[b] = __half22float2(glob[u + 256*b]);
        fft8<false>(v);
        #pragma unroll
        for (int j = 1; j < 8; j++) v[j] = cmul(v[j], W[j]);
        #pragma unroll
        for (int j = 0; j < 8; j++) sm[PAD(j*256 + u)] = v[j];
    }
    __syncthreads();

    // S2: radix-8 over stride 32, twiddle W_256^{c*j2}
    { const int j = u >> 5, c = u & 31, base = j*256 + c;
      twpow(W, twid(128, c));
      #pragma unroll
      for (int rr = 0; rr < 2; rr++) {
        float2* sm = rr ? smB : smA;
        #pragma unroll
        for (int d = 0; d < 8; d++) v[d] = sm[PAD(base + 32*d)];
        fft8<false>(v);
        #pragma unroll
        for (int j2 = 1; j2 < 8; j2++) v[j2] = cmul(v[j2], W[j2]);
        #pragma unroll
        for (int j2 = 0; j2 < 8; j2++) sm[PAD(j*256 + j2*32 + c)] = v[j2];
      }
    }
    __syncthreads();

    // S3: radix-8 over stride 4, twiddle W_32^{e*j3}
    { const int j = u >> 5, j2 = (u >> 2) & 7, e = u & 3, base = j*256 + j2*32 + e;
      twpow(W, twid(16, e));
      #pragma unroll
      for (int rr = 0; rr < 2; rr++) {
        float2* sm = rr ? smB : smA;
        #pragma unroll
        for (int f = 0; f < 8; f++) v[f] = sm[PAD(base + 4*f)];
        fft8<false>(v);
        #pragma unroll
        for (int j3 = 1; j3 < 8; j3++) v[j3] = cmul(v[j3], W[j3]);
        #pragma unroll
        for (int j3 = 0; j3 < 8; j3++) sm[PAD(base + 4*j3)] = v[j3];
      }
    }
    __syncthreads();

    if (g != 0) {
        // FUSED S4 + pointwise + IS4 in registers, ROW A result only.
        // Thread u owns A groups {u, u+256}; complement of A element 4t+e is
        // B group 511-t element 3-e (position 2047-(4t+e)). smB read-only;
        // each smA group written only by its owner -> no sync inside.
        #pragma unroll
        for (int gi = 0; gi < 2; gi++) {
            const int t = u + 256*gi;
            float2 a4[4], b4[4], ya[4];
            #pragma unroll
            for (int e = 0; e < 4; e++) {
                a4[e] = smA[PAD(4*t + e)];
                b4[e] = smB[PAD(4*(511 - t) + e)];
            }
            fft4<false>(a4);
            fft4<false>(b4);
            #pragma unroll
            for (int e = 0; e < 4; e++) ya[e] = pw(a4[e], b4[3-e]);
            fft4<true>(ya);
            #pragma unroll
            for (int e = 0; e < 4; e++) smA[PAD(4*t + e)] = ya[e];
        }
    } else {
        // g==0: S4 both rows (stored), explicit pairing, IS4 both rows.
        #pragma unroll
        for (int rr = 0; rr < 2; rr++) {
            float2* sm = rr ? smB : smA;
            #pragma unroll
            for (int gi = 0; gi < 2; gi++) {
                const int grp = u + 256*gi;
                float2 w4[4];
                #pragma unroll
                for (int e = 0; e < 4; e++) w4[e] = sm[PAD(4*grp + e)];
                fft4<false>(w4);
                #pragma unroll
                for (int m = 0; m < 4; m++) sm[PAD(4*grp + m)] = w4[m];
            }
        }
        __syncthreads();
        // row 0 pairs with itself at k2' = (2048-k2) mod 2048 (k2-space);
        // row 32 self-pairs position-locally.
        #pragma unroll
        for (int e = 0; e < 4; e++) {
            int k2 = 4*u + e;                    // 0..1023
            int pa = POS(k2);
            int pb = POS((2048 - k2) & 2047);
            float2 Za = smA[PAD(pa)];
            float2 Zb = smA[PAD(pb)];
            float2 Y = pw(Za, Zb);
            smA[PAD(pa)] = Y;
            smA[PAD(pb)] = cconj(Y);
        }
        if (u == 0) {                            // k2 = 1024 self-pair, pos = 2
            float2 Za = smA[PAD(2)];
            smA[PAD(2)] = pw(Za, Za);
        }
        #pragma unroll
        for (int e = 0; e < 4; e++) {
            int p = 4*u + e;                     // 0..1023
            float2 Za = smB[PAD(p)];
            float2 Zb = smB[PAD(2047 - p)];
            float2 Y = pw(Za, Zb);
            smB[PAD(p)]        = Y;
            smB[PAD(2047 - p)] = cconj(Y);
        }
        __syncthreads();
        // IS4 (both rows)
        #pragma unroll
        for (int rr = 0; rr < 2; rr++) {
            float2* sm = rr ? smB : smA;
            #pragma unroll
            for (int gi = 0; gi < 2; gi++) {
                const int grp = u + 256*gi;
                float2 w4[4];
                #pragma unroll
                for (int e = 0; e < 4; e++) w4[e] = sm[PAD(4*grp + e)];
                fft4<true>(w4);
                #pragma unroll
                for (int e = 0; e < 4; e++) sm[PAD(4*grp + e)] = w4[e];
            }
        }
    }
    __syncthreads();

    // IS3: conj twiddle W_32^{-e*j3}, inverse radix-8 over j3 -> f
    { const int j = u >> 5, j2 = (u >> 2) & 7, e = u & 3, base = j*256 + j2*32 + e;
      twpow(W, twidc(16, e));
      for (int rr = 0; rr < nInv; rr++) {
        float2* sm = rr ? smB : smA;
        #pragma unroll
        for (int j3 = 0; j3 < 8; j3++) v[j3] = sm[PAD(base + 4*j3)];
        #pragma unroll
        for (int j3 = 1; j3 < 8; j3++) v[j3] = cmul(v[j3], W[j3]);
        fft8<true>(v);
        #pragma unroll
        for (int f = 0; f < 8; f++) sm[PAD(base + 4*f)] = v[f];
      }
    }
    __syncthreads();

    // IS2: conj twiddle W_256^{-c*j2}, inverse radix-8 over j2 -> d
    { const int j = u >> 5, c = u & 31, base = j*256 + c;
      twpow(W, twidc(128, c));
      for (int rr = 0; rr < nInv; rr++) {
        float2* sm = rr ? smB : smA;
        #pragma unroll
        for (int j2 = 0; j2 < 8; j2++) v[j2] = sm[PAD(base + 32*j2)];
        #pragma unroll
        for (int j2 = 1; j2 < 8; j2++) v[j2] = cmul(v[j2], W[j2]);
        fft8<true>(v);
        #pragma unroll
        for (int d = 0; d < 8; d++) sm[PAD(base + 32*d)] = v[d];
      }
    }
    __syncthreads();

    // IS1: conj twiddle W_2048^{-a*j}, inverse radix-8 over j -> b,
    // conj inter-step twiddle W_N^{-row*(b*256+a)} with 1/N folded in,
    // store as fp16 (rows <= 32 only).
    { const int a = u;
      twpow(W, twidc(1024, a));
      const float SC = 1.0f / (float)NN;
      for (int rr = 0; rr < nInv; rr++) {
        float2* sm = rr ? smB : smA;
        const int myrow = rr ? rowB : rowA;
        #pragma unroll
        for (int j = 0; j < 8; j++) v[j] = sm[PAD(j*256 + a)];
        #pragma unroll
        for (int j = 1; j < 8; j++) v[j] = cmul(v[j], W[j]);
        fft8<true>(v);
        float2 acc  = twidc(NHALF, myrow * a);
        acc.x *= SC; acc.y *= SC;               // scale survives the chain
        float2 step = twidc(NHALF, 256 * myrow);
        __half2* gh = g_h + (size_t)s * (33 * N2) + myrow * N2;
        #pragma unroll
        for (int b = 0; b < 8; b++) {
            float2 y = cmul(v[b], acc);
            gh[b*256 + a] = __floats2half2_rn(y.x, y.y);
            acc = cmul(acc, step);
        }
      }
    }
}

// ---------------------------------------------------------------------------
// Stage 3: inverse 64-pt FFT along k1 (two register radix-8 passes, one smem
// exchange), write real part of n1 < 32 only (1/N already folded in stage 2).
// Rows 33..63 reconstructed as conj(row 64-r); reads fp16.
// ---------------------------------------------------------------------------
__global__ void __launch_bounds__(256) k_stage3(float* __restrict__ out) {
    __shared__ float2 sm[64 * 32];
    const int s   = blockIdx.y;
    const int col = threadIdx.x & 31;
    const int j   = threadIdx.x >> 5;
    const int n2  = blockIdx.x * 32 + col;
    const __half2* gh = g_h + (size_t)s * (33 * N2);

    float2 v[8];
    #pragma unroll
    for (int m = 0; m < 8; m++) {
        int rr = j + 8*m;
        if (rr <= 32) {
            v[m] = __half22float2(gh[rr * N2 + n2]);
        } else {
            float2 t = __half22float2(gh[(64 - rr) * N2 + n2]);
            v[m] = make_float2(t.x, -t.y);
        }
    }
    fft8<true>(v);                               // over m -> a
    #pragma unroll
    for (int a = 0; a < 8; a++) sm[(a*8 + j)*32 + col] = v[a];
    __syncthreads();

    const int a = threadIdx.x >> 5;
    #pragma unroll
    for (int q = 0; q < 8; q++) v[q] = sm[(a*8 + q)*32 + col];
    { float2 W[8];
      twpow(W, twidc(32, a));
      #pragma unroll
      for (int q = 1; q < 8; q++) v[q] = cmul(v[q], W[q]);
    }
    fft8<true>(v);                               // over j -> b ; n1 = a + 8b

    float* os = out + (size_t)s * T_LEN;
    #pragma unroll
    for (int b = 0; b < 4; b++)
        os[(a + 8*b) * N2 + n2] = v[b].x;
}

extern "C" void kernel_launch(void* const* d_in, const int* in_sizes, int n_in,
                              void* d_out, int out_size) {
    const float* x = (const float*)d_in[0];
    const float* h = (const float*)d_in[1];
    float* out = (float*)d_out;

    k_init_tw<<<NN / 256, 256>>>();
    k_stage1<<<dim3(N2 / 32, SEQ), 256>>>(x, h);
    k_stage2<<<dim3(32, SEQ), 256>>>();
    k_stage3<<<dim3(N2 / 32, SEQ), 256>>>(out);
}

// round 13
// speedup vs baseline: 2.3803x; 1.0324x over previous
#include <cuda_runtime.h>
#include <cuda_bf16.h>
#include <cuda_fp16.h>

#define SEQ   512
#define T_LEN 65536
#define NN    131072
#define NHALF 65536
#define N2    2048

// Scratch (device globals; no allocations allowed)
__device__ __half2 g_zh[(size_t)SEQ * NN];      // 256 MiB fp16 stage1->2 buffer
__device__ __half2 g_h[(size_t)SEQ * 33 * N2];  // 138 MiB fp16 stage2->3 buffer
__device__ float2 g_tw[NN];                     // g_tw[h+p] = exp(-i*pi*p/h)

static __device__ __forceinline__ float2 cmul(float2 a, float2 b) {
    return make_float2(fmaf(a.x, b.x, -a.y * b.y), fmaf(a.x, b.y, a.y * b.x));
}
static __device__ __forceinline__ float2 cadd(float2 a, float2 b) { return make_float2(a.x+b.x, a.y+b.y); }
static __device__ __forceinline__ float2 csub(float2 a, float2 b) { return make_float2(a.x-b.x, a.y-b.y); }
static __device__ __forceinline__ float2 mulnI(float2 a) { return make_float2(a.y, -a.x); }   // * (-i)
static __device__ __forceinline__ float2 mulpI(float2 a) { return make_float2(-a.y, a.x); }   // * (+i)
static __device__ __forceinline__ float2 cconj(float2 a) { return make_float2(a.x, -a.y); }

// W_{2*Mhalf}^q  for q in [0, 2*Mhalf)
static __device__ __forceinline__ float2 twid(int Mhalf, int q) {
    if (q < Mhalf) return g_tw[Mhalf + q];
    float2 t = g_tw[q];                    // == g_tw[Mhalf + (q - Mhalf)]
    return make_float2(-t.x, -t.y);
}
// conj(W_{2*Mhalf}^q)
static __device__ __forceinline__ float2 twidc(int Mhalf, int q) {
    if (q < Mhalf) { float2 t = g_tw[Mhalf + q]; return make_float2(t.x, -t.y); }
    float2 t = g_tw[q];
    return make_float2(-t.x, t.y);
}

// Powers W[j] = w^j, j=1..7, built with a depth-3 tree (6 cmuls, 1 load).
static __device__ __forceinline__ void twpow(float2 W[8], float2 w) {
    W[1] = w;
    W[2] = cmul(w, w);
    W[3] = cmul(W[2], w);
    W[4] = cmul(W[2], W[2]);
    W[5] = cmul(W[2], W[3]);
    W[6] = cmul(W[3], W[3]);
    W[7] = cmul(W[3], W[4]);
}

// 8-pt DFT, natural in/out. INV => conjugated twiddles (unnormalized inverse).
template<bool INV>
static __device__ __forceinline__ void fft8(float2 z[8]) {
    const float C = 0.70710678118654752440f;
    float2 t0=cadd(z[0],z[4]), t1=cadd(z[1],z[5]), t2=cadd(z[2],z[6]), t3=cadd(z[3],z[7]);
    float2 s0=csub(z[0],z[4]), s1=csub(z[1],z[5]), s2=csub(z[2],z[6]), s3=csub(z[3],z[7]);
    if (!INV) {
        s1 = cmul(s1, make_float2(C,-C)); s2 = mulnI(s2); s3 = cmul(s3, make_float2(-C,-C));
    } else {
        s1 = cmul(s1, make_float2(C, C)); s2 = mulpI(s2); s3 = cmul(s3, make_float2(-C, C));
    }
    float2 a0=cadd(t0,t2), a1=csub(t0,t2), a2=cadd(t1,t3), a3=csub(t1,t3);
    a3 = INV ? mulpI(a3) : mulnI(a3);
    float2 b0=cadd(s0,s2), b1=csub(s0,s2), b2=cadd(s1,s3), b3=csub(s1,s3);
    b3 = INV ? mulpI(b3) : mulnI(b3);
    z[0]=cadd(a0,a2); z[4]=csub(a0,a2);
    z[2]=cadd(a1,a3); z[6]=csub(a1,a3);
    z[1]=cadd(b0,b2); z[5]=csub(b0,b2);
    z[3]=cadd(b1,b3); z[7]=csub(b1,b3);
}

template<bool INV>
static __device__ __forceinline__ void fft4(float2 z[4]) {
    float2 a0=cadd(z[0],z[2]), a1=csub(z[0],z[2]);
    float2 a2=cadd(z[1],z[3]), a3=csub(z[1],z[3]);
    a3 = INV ? mulpI(a3) : mulnI(a3);
    z[0]=cadd(a0,a2); z[2]=csub(a0,a2);
    z[1]=cadd(a1,a3); z[3]=csub(a1,a3);
}

// Hermitian unpack + pointwise: Za = Z[k], Zb = Z[N-k]; returns Y[k] = X[k]*H[k]
static __device__ __forceinline__ float2 pw(float2 Za, float2 Zb) {
    float2 X = make_float2(0.5f*(Za.x+Zb.x),  0.5f*(Za.y-Zb.y));
    float2 H = make_float2(0.5f*(Za.y+Zb.y), -0.5f*(Za.x-Zb.x));
    return cmul(X, H);
}

#define PAD(p) ((p) + (((p) >> 5) << 2))
#define POS(k2) ((((k2)&7)<<8) + ((((k2)>>3)&7)<<5) + ((((k2)>>6)&7)<<2) + ((k2)>>9))

__global__ void k_init_tw() {
    int idx = blockIdx.x * blockDim.x + threadIdx.x;
    if (idx >= NN) return;
    if (idx == 0) { g_tw[0] = make_float2(1.0f, 0.0f); return; }
    int h = 1 << (31 - __clz(idx));
    int p = idx - h;
    float s, c;
    sincospif(-(float)p / (float)h, &s, &c);
    g_tw[idx] = make_float2(c, s);
}

// ---------------------------------------------------------------------------
// Stage 1: pack z = bf16(x) + i*h (rows n1>=32 are zero) + 64-pt FFT along n1
// (two register radix-8 passes, one smem exchange) + twiddle W_N^{k1*n2}.
// Output (fp16): g_zh[s][k1*2048 + n2]
// ---------------------------------------------------------------------------
__global__ void __launch_bounds__(256) k_stage1(const float* __restrict__ x,
                                                const float* __restrict__ hk) {
    __shared__ float2 sm[64 * 32];
    const int s   = blockIdx.y;
    const int col = threadIdx.x & 31;
    const int a   = threadIdx.x >> 5;          // 0..7
    const int n2  = blockIdx.x * 32 + col;
    const float* xs = x  + (size_t)s * T_LEN;
    const float* hs = hk + (size_t)s * T_LEN;

    float2 v[8];
    #pragma unroll
    for (int b = 0; b < 4; b++) {
        int n = (a + 8*b) * N2 + n2;           // < 65536 always
        v[b] = make_float2(__bfloat162float(__float2bfloat16_rn(xs[n])), hs[n]);
    }
    // fft8 over b with upper half zero (t = z, s = z)
    {
        const float C = 0.70710678118654752440f;
        float2 t0=v[0], t1=v[1], t2=v[2], t3=v[3];
        float2 s0=v[0];
        float2 s1=cmul(v[1], make_float2(C,-C));
        float2 s2=mulnI(v[2]);
        float2 s3=cmul(v[3], make_float2(-C,-C));
        float2 a0=cadd(t0,t2), a1=csub(t0,t2), a2=cadd(t1,t3), a3=mulnI(csub(t1,t3));
        float2 b0=cadd(s0,s2), b1=csub(s0,s2), b2=cadd(s1,s3), b3=mulnI(csub(s1,s3));
        v[0]=cadd(a0,a2); v[4]=csub(a0,a2);
        v[2]=cadd(a1,a3); v[6]=csub(a1,a3);
        v[1]=cadd(b0,b2); v[5]=csub(b0,b2);
        v[3]=cadd(b1,b3); v[7]=csub(b1,b3);
    }
    // twiddle W_64^{a*j}
    {
        float2 W[8];
        twpow(W, twid(32, a));
        #pragma unroll
        for (int j = 1; j < 8; j++) v[j] = cmul(v[j], W[j]);
    }
    #pragma unroll
    for (int j = 0; j < 8; j++) sm[(j*8 + a)*32 + col] = v[j];
    __syncthreads();

    const int j = a;                            // phase-2 role
    #pragma unroll
    for (int q = 0; q < 8; q++) v[q] = sm[(j*8 + q)*32 + col];
    fft8<false>(v);                             // over a -> m ; k1 = j + 8m

    __half2* zs = g_zh + (size_t)s * NN;
    {
        float2 acc  = twid(NHALF, n2 * j);      // n2*j < 65536
        float2 step = twid(NHALF, 8 * n2);
        #pragma unroll
        for (int m = 0; m < 8; m++) {
            int k1 = j + 8*m;
            float2 y = cmul(v[m], acc);
            zs[k1 * N2 + n2] = __floats2half2_rn(y.x, y.y);
            acc = cmul(acc, step);
        }
    }
}

// ---------------------------------------------------------------------------
// Stage 2 (256 threads, 4 blocks/SM, zero idle): pair {g, 64-g} ({0,32} g==0).
// Rows sequential within each stage; twiddle trees shared across rows.
// Forward 2 rows -> fused S4+pointwise+IS4 (row A) -> inverse row A only
// (realness) -> store rows 0..32 as fp16 with 1/N folded in.
// ---------------------------------------------------------------------------
__global__ void __launch_bounds__(256, 4) k_stage2() {
    __shared__ float2 smA[2304];
    __shared__ float2 smB[2304];
    const int s = blockIdx.y;
    const int g = blockIdx.x;                   // 0..31
    const int rowA = g;
    const int rowB = (g == 0) ? 32 : 64 - g;
    const int u = threadIdx.x;                  // 0..255
    const int nInv = (g == 0) ? 2 : 1;
    const __half2* zb = g_zh + (size_t)s * NN;

    float2 v[8], W[8];

    // S1: radix-8 over stride 256, twiddle W_2048^{u*j} (shared by both rows)
    twpow(W, twid(1024, u));
    #pragma unroll
    for (int rr = 0; rr < 2; rr++) {
        const __half2* glob = zb + (rr ? rowB : rowA) * N2;
        float2* sm = rr ? smB : smA;
        #pragma unroll
        for (int b = 0; b < 8; b++) v[b] = __half22float2(glob[u + 256*b]);
        fft8<false>(v);
        #pragma unroll
        for (int j = 1; j < 8; j++) v[j] = cmul(v[j], W[j]);
        #pragma unroll
        for (int j = 0; j < 8; j++) sm[PAD(j*256 + u)] = v[j];
    }
    __syncthreads();

    // S2: radix-8 over stride 32, twiddle W_256^{c*j2}
    { const int j = u >> 5, c = u & 31, base = j*256 + c;
      twpow(W, twid(128, c));
      #pragma unroll
      for (int rr = 0; rr < 2; rr++) {
        float2* sm = rr ? smB : smA;
        #pragma unroll
        for (int d = 0; d < 8; d++) v[d] = sm[PAD(base + 32*d)];
        fft8<false>(v);
        #pragma unroll
        for (int j2 = 1; j2 < 8; j2++) v[j2] = cmul(v[j2], W[j2]);
        #pragma unroll
        for (int j2 = 0; j2 < 8; j2++) sm[PAD(j*256 + j2*32 + c)] = v[j2];
      }
    }
    __syncthreads();

    // S3: radix-8 over stride 4, twiddle W_32^{e*j3}
    { const int j = u >> 5, j2 = (u >> 2) & 7, e = u & 3, base = j*256 + j2*32 + e;
      twpow(W, twid(16, e));
      #pragma unroll
      for (int rr = 0; rr < 2; rr++) {
        float2* sm = rr ? smB : smA;
        #pragma unroll
        for (int f = 0; f < 8; f++) v[f] = sm[PAD(base + 4*f)];
        fft8<false>(v);
        #pragma unroll
        for (int j3 = 1; j3 < 8; j3++) v[j3] = cmul(v[j3], W[j3]);
        #pragma unroll
        for (int j3 = 0; j3 < 8; j3++) sm[PAD(base + 4*j3)] = v[j3];
      }
    }
    __syncthreads();

    if (g != 0) {
        // FUSED S4 + pointwise + IS4 in registers, ROW A result only.
        #pragma unroll
        for (int gi = 0; gi < 2; gi++) {
            const int t = u + 256*gi;
            float2 a4[4], b4[4], ya[4];
            #pragma unroll
            for (int e = 0; e < 4; e++) {
                a4[e] = smA[PAD(4*t + e)];
                b4[e] = smB[PAD(4*(511 - t) + e)];
            }
            fft4<false>(a4);
            fft4<false>(b4);
            #pragma unroll
            for (int e = 0; e < 4; e++) ya[e] = pw(a4[e], b4[3-e]);
            fft4<true>(ya);
            #pragma unroll
            for (int e = 0; e < 4; e++) smA[PAD(4*t + e)] = ya[e];
        }
    } else {
        // g==0: S4 both rows (stored), explicit pairing, IS4 both rows.
        #pragma unroll
        for (int rr = 0; rr < 2; rr++) {
            float2* sm = rr ? smB : smA;
            #pragma unroll
            for (int gi = 0; gi < 2; gi++) {
                const int grp = u + 256*gi;
                float2 w4[4];
                #pragma unroll
                for (int e = 0; e < 4; e++) w4[e] = sm[PAD(4*grp + e)];
                fft4<false>(w4);
                #pragma unroll
                for (int m = 0; m < 4; m++) sm[PAD(4*grp + m)] = w4[m];
            }
        }
        __syncthreads();
        #pragma unroll
        for (int e = 0; e < 4; e++) {
            int k2 = 4*u + e;                    // 0..1023
            int pa = POS(k2);
            int pb = POS((2048 - k2) & 2047);
            float2 Za = smA[PAD(pa)];
            float2 Zb = smA[PAD(pb)];
            float2 Y = pw(Za, Zb);
            smA[PAD(pa)] = Y;
            smA[PAD(pb)] = cconj(Y);
        }
        if (u == 0) {                            // k2 = 1024 self-pair, pos = 2
            float2 Za = smA[PAD(2)];
            smA[PAD(2)] = pw(Za, Za);
        }
        #pragma unroll
        for (int e = 0; e < 4; e++) {
            int p = 4*u + e;                     // 0..1023
            float2 Za = smB[PAD(p)];
            float2 Zb = smB[PAD(2047 - p)];
            float2 Y = pw(Za, Zb);
            smB[PAD(p)]        = Y;
            smB[PAD(2047 - p)] = cconj(Y);
        }
        __syncthreads();
        #pragma unroll
        for (int rr = 0; rr < 2; rr++) {
            float2* sm = rr ? smB : smA;
            #pragma unroll
            for (int gi = 0; gi < 2; gi++) {
                const int grp = u + 256*gi;
                float2 w4[4];
                #pragma unroll
                for (int e = 0; e < 4; e++) w4[e] = sm[PAD(4*grp + e)];
                fft4<true>(w4);
                #pragma unroll
                for (int e = 0; e < 4; e++) sm[PAD(4*grp + e)] = w4[e];
            }
        }
    }
    __syncthreads();

    // IS3: conj twiddle W_32^{-e*j3}, inverse radix-8 over j3 -> f
    { const int j = u >> 5, j2 = (u >> 2) & 7, e = u & 3, base = j*256 + j2*32 + e;
      twpow(W, twidc(16, e));
      for (int rr = 0; rr < nInv; rr++) {
        float2* sm = rr ? smB : smA;
        #pragma unroll
        for (int j3 = 0; j3 < 8; j3++) v[j3] = sm[PAD(base + 4*j3)];
        #pragma unroll
        for (int j3 = 1; j3 < 8; j3++) v[j3] = cmul(v[j3], W[j3]);
        fft8<true>(v);
        #pragma unroll
        for (int f = 0; f < 8; f++) sm[PAD(base + 4*f)] = v[f];
      }
    }
    __syncthreads();

    // IS2: conj twiddle W_256^{-c*j2}, inverse radix-8 over j2 -> d
    { const int j = u >> 5, c = u & 31, base = j*256 + c;
      twpow(W, twidc(128, c));
      for (int rr = 0; rr < nInv; rr++) {
        float2* sm = rr ? smB : smA;
        #pragma unroll
        for (int j2 = 0; j2 < 8; j2++) v[j2] = sm[PAD(base + 32*j2)];
        #pragma unroll
        for (int j2 = 1; j2 < 8; j2++) v[j2] = cmul(v[j2], W[j2]);
        fft8<true>(v);
        #pragma unroll
        for (int d = 0; d < 8; d++) sm[PAD(base + 32*d)] = v[d];
      }
    }
    __syncthreads();

    // IS1: conj twiddle W_2048^{-a*j}, inverse radix-8 over j -> b,
    // conj inter-step twiddle W_N^{-row*(b*256+a)} with 1/N folded in,
    // store as fp16 (rows <= 32 only).
    { const int a = u;
      twpow(W, twidc(1024, a));
      const float SC = 1.0f / (float)NN;
      for (int rr = 0; rr < nInv; rr++) {
        float2* sm = rr ? smB : smA;
        const int myrow = rr ? rowB : rowA;
        #pragma unroll
        for (int j = 0; j < 8; j++) v[j] = sm[PAD(j*256 + a)];
        #pragma unroll
        for (int j = 1; j < 8; j++) v[j] = cmul(v[j], W[j]);
        fft8<true>(v);
        float2 acc  = twidc(NHALF, myrow * a);
        acc.x *= SC; acc.y *= SC;               // scale survives the chain
        float2 step = twidc(NHALF, 256 * myrow);
        __half2* gh = g_h + (size_t)s * (33 * N2) + myrow * N2;
        #pragma unroll
        for (int b = 0; b < 8; b++) {
            float2 y = cmul(v[b], acc);
            gh[b*256 + a] = __floats2half2_rn(y.x, y.y);
            acc = cmul(acc, step);
        }
      }
    }
}

// ---------------------------------------------------------------------------
// Stage 3 (real-output half-size IFFT): per column n2, build
//   G[k] = (U[k] + conj(U[32-k])) + i*w^k*(U[k] - conj(U[32-k])), w=e^{2pi i/64}
// from U rows 0..32 (fp16), then z = IFFT_32(G): y[2n]=Re z[n], y[2n+1]=Im z[n].
// We keep only y[0..31] (causal half) => store z[n] for n < 16 only.
// 32 = 8x4: 4 threads/col; thread m holds G[m+4t] -> fft8<inv> over t ->
// twiddle W_32^{n0*m} -> exchange -> fft4<inv> over m -> guarded stores.
// 1/N already folded in stage 2.
// ---------------------------------------------------------------------------
__global__ void __launch_bounds__(256) k_stage3(float* __restrict__ out) {
    __shared__ float2 sm[32 * 64];
    const int s   = blockIdx.y;
    const int col = threadIdx.x & 63;
    const int m   = threadIdx.x >> 6;            // 0..3
    const int n2  = blockIdx.x * 64 + col;
    const __half2* gh = g_h + (size_t)s * (33 * N2);

    float2 v[8];
    // Build G[m+4t], t=0..7
    #pragma unroll
    for (int t = 0; t < 8; t++) {
        int k = m + 4*t;                         // 0..31
        float2 Uk = __half22float2(gh[k * N2 + n2]);
        float2 Uc = __half22float2(gh[(32 - k) * N2 + n2]);
        Uc.y = -Uc.y;                            // conj(U[32-k])
        float2 sum  = cadd(Uk, Uc);
        float2 diff = csub(Uk, Uc);
        float2 wk = twidc(32, k);                // e^{+2pi i k/64}
        v[t] = cadd(sum, mulpI(cmul(wk, diff))); // sum + i*w^k*diff
    }
    fft8<true>(v);                               // over t -> n0 (natural order)
    // twiddle W_32^{n0*m}, W_32 = e^{+2pi i/32}
    { float2 W[8];
      twpow(W, twidc(16, m));
      #pragma unroll
      for (int n0 = 1; n0 < 8; n0++) v[n0] = cmul(v[n0], W[n0]);
    }
    #pragma unroll
    for (int n0 = 0; n0 < 8; n0++) sm[(n0*4 + m)*64 + col] = v[n0];
    __syncthreads();

    // fft4<inv> over m for n0 in {2q, 2q+1}; keep z[n] only for n < 16
    const int q = m;                             // 0..3
    float* os = out + (size_t)s * T_LEN;
    #pragma unroll
    for (int h2 = 0; h2 < 2; h2++) {
        const int n0 = 2*q + h2;                 // 0..7
        float2 w4[4];
        #pragma unroll
        for (int mm = 0; mm < 4; mm++) w4[mm] = sm[(n0*4 + mm)*64 + col];
        fft4<true>(w4);                          // over m -> s4 ; n = n0 + 8*s4
        #pragma unroll
        for (int s4 = 0; s4 < 2; s4++) {         // n < 16 => y rows < 32 only
            int n = n0 + 8*s4;                   // 0..15
            os[(2*n)     * N2 + n2] = w4[s4].x;  // y[2n]
            os[(2*n + 1) * N2 + n2] = w4[s4].y;  // y[2n+1]
        }
    }
}

extern "C" void kernel_launch(void* const* d_in, const int* in_sizes, int n_in,
                              void* d_out, int out_size) {
    const float* x = (const float*)d_in[0];
    const float* h = (const float*)d_in[1];
    float* out = (float*)d_out;

    k_init_tw<<<NN / 256, 256>>>();
    k_stage1<<<dim3(N2 / 32, SEQ), 256>>>(x, h);
    k_stage2<<<dim3(32, SEQ), 256>>>();
    k_stage3<<<dim3(N2 / 64, SEQ), 256>>>(out);
}

// round 14
// speedup vs baseline: 2.4417x; 1.0258x over previous
#include <cuda_runtime.h>
#include <cuda_bf16.h>
#include <cuda_fp16.h>

#define SEQ   512
#define T_LEN 65536
#define NN    131072
#define NHALF 65536
#define N2    2048

// Scratch (device globals; no allocations allowed)
__device__ __half2 g_zh[(size_t)SEQ * NN];      // 256 MiB fp16 stage1->2 buffer
__device__ __half2 g_h[(size_t)SEQ * 33 * N2];  // 138 MiB fp16 stage2->3 buffer
__device__ float2 g_tw[NN];                     // g_tw[h+p] = exp(-i*pi*p/h)

static __device__ __forceinline__ float2 cmul(float2 a, float2 b) {
    return make_float2(fmaf(a.x, b.x, -a.y * b.y), fmaf(a.x, b.y, a.y * b.x));
}
static __device__ __forceinline__ float2 cadd(float2 a, float2 b) { return make_float2(a.x+b.x, a.y+b.y); }
static __device__ __forceinline__ float2 csub(float2 a, float2 b) { return make_float2(a.x-b.x, a.y-b.y); }
static __device__ __forceinline__ float2 mulnI(float2 a) { return make_float2(a.y, -a.x); }   // * (-i)
static __device__ __forceinline__ float2 mulpI(float2 a) { return make_float2(-a.y, a.x); }   // * (+i)
static __device__ __forceinline__ float2 cconj(float2 a) { return make_float2(a.x, -a.y); }

// W_{2*Mhalf}^q  for q in [0, 2*Mhalf)
static __device__ __forceinline__ float2 twid(int Mhalf, int q) {
    if (q < Mhalf) return g_tw[Mhalf + q];
    float2 t = g_tw[q];                    // == g_tw[Mhalf + (q - Mhalf)]
    return make_float2(-t.x, -t.y);
}
// conj(W_{2*Mhalf}^q)
static __device__ __forceinline__ float2 twidc(int Mhalf, int q) {
    if (q < Mhalf) { float2 t = g_tw[Mhalf + q]; return make_float2(t.x, -t.y); }
    float2 t = g_tw[q];
    return make_float2(-t.x, t.y);
}

// Powers W[j] = w^j, j=1..7, built with a depth-3 tree (6 cmuls, 1 load).
static __device__ __forceinline__ void twpow(float2 W[8], float2 w) {
    W[1] = w;
    W[2] = cmul(w, w);
    W[3] = cmul(W[2], w);
    W[4] = cmul(W[2], W[2]);
    W[5] = cmul(W[2], W[3]);
    W[6] = cmul(W[3], W[3]);
    W[7] = cmul(W[3], W[4]);
}

// 8-pt DFT, natural in/out. INV => conjugated twiddles (unnormalized inverse).
template<bool INV>
static __device__ __forceinline__ void fft8(float2 z[8]) {
    const float C = 0.70710678118654752440f;
    float2 t0=cadd(z[0],z[4]), t1=cadd(z[1],z[5]), t2=cadd(z[2],z[6]), t3=cadd(z[3],z[7]);
    float2 s0=csub(z[0],z[4]), s1=csub(z[1],z[5]), s2=csub(z[2],z[6]), s3=csub(z[3],z[7]);
    if (!INV) {
        s1 = cmul(s1, make_float2(C,-C)); s2 = mulnI(s2); s3 = cmul(s3, make_float2(-C,-C));
    } else {
        s1 = cmul(s1, make_float2(C, C)); s2 = mulpI(s2); s3 = cmul(s3, make_float2(-C, C));
    }
    float2 a0=cadd(t0,t2), a1=csub(t0,t2), a2=cadd(t1,t3), a3=csub(t1,t3);
    a3 = INV ? mulpI(a3) : mulnI(a3);
    float2 b0=cadd(s0,s2), b1=csub(s0,s2), b2=cadd(s1,s3), b3=csub(s1,s3);
    b3 = INV ? mulpI(b3) : mulnI(b3);
    z[0]=cadd(a0,a2); z[4]=csub(a0,a2);
    z[2]=cadd(a1,a3); z[6]=csub(a1,a3);
    z[1]=cadd(b0,b2); z[5]=csub(b0,b2);
    z[3]=cadd(b1,b3); z[7]=csub(b1,b3);
}

template<bool INV>
static __device__ __forceinline__ void fft4(float2 z[4]) {
    float2 a0=cadd(z[0],z[2]), a1=csub(z[0],z[2]);
    float2 a2=cadd(z[1],z[3]), a3=csub(z[1],z[3]);
    a3 = INV ? mulpI(a3) : mulnI(a3);
    z[0]=cadd(a0,a2); z[2]=csub(a0,a2);
    z[1]=cadd(a1,a3); z[3]=csub(a1,a3);
}

// 16-pt DFT, natural in/out, via 4x4 Cooley-Tukey. INV => conj twiddles.
template<bool INV>
static __device__ __forceinline__ void fft16(float2 z[16]) {
    const float C1 = 0.92387953251128675613f;   // cos(pi/8)
    const float S1 = 0.38268343236508977173f;   // sin(pi/8)
    const float R  = 0.70710678118654752440f;
    const float2 W1 = INV ? make_float2(C1,  S1) : make_float2(C1, -S1);
    const float2 W2 = INV ? make_float2(R,   R ) : make_float2(R,  -R );
    const float2 W3 = INV ? make_float2(S1,  C1) : make_float2(S1, -C1);
    const float2 W6 = INV ? make_float2(-R,  R ) : make_float2(-R, -R );
    const float2 W9 = INV ? make_float2(-C1,-S1) : make_float2(-C1, S1);
    float2 t[16];
    #pragma unroll
    for (int b = 0; b < 4; b++) {
        float2 q[4] = { z[b], z[4+b], z[8+b], z[12+b] };
        fft4<INV>(q);
        if (b == 1) { q[1]=cmul(q[1],W1); q[2]=cmul(q[2],W2); q[3]=cmul(q[3],W3); }
        if (b == 2) { q[1]=cmul(q[1],W2); q[2]= INV?mulpI(q[2]):mulnI(q[2]); q[3]=cmul(q[3],W6); }
        if (b == 3) { q[1]=cmul(q[1],W3); q[2]=cmul(q[2],W6); q[3]=cmul(q[3],W9); }
        t[b] = q[0]; t[4+b] = q[1]; t[8+b] = q[2]; t[12+b] = q[3];
    }
    #pragma unroll
    for (int c = 0; c < 4; c++) {
        float2 q[4] = { t[4*c+0], t[4*c+1], t[4*c+2], t[4*c+3] };
        fft4<INV>(q);
        z[c] = q[0]; z[c+4] = q[1]; z[c+8] = q[2]; z[c+12] = q[3];
    }
}

// Hermitian unpack + pointwise: Za = Z[k], Zb = Z[N-k]; returns Y[k] = X[k]*H[k]
static __device__ __forceinline__ float2 pw(float2 Za, float2 Zb) {
    float2 X = make_float2(0.5f*(Za.x+Zb.x),  0.5f*(Za.y-Zb.y));
    float2 H = make_float2(0.5f*(Za.y+Zb.y), -0.5f*(Za.x-Zb.x));
    return cmul(X, H);
}

#define PAD(p) ((p) + (((p) >> 5) << 2))
// digit-reversed position for plan 16(str128),16(str8),8(str1):
// k2 = j + 16*j2 + 256*j3  ->  p = 128*j + 8*j2 + j3
#define POS16(k2) ((((k2) & 15) << 7) + ((((k2) >> 4) & 15) << 3) + ((k2) >> 8))

__global__ void k_init_tw() {
    int idx = blockIdx.x * blockDim.x + threadIdx.x;
    if (idx >= NN) return;
    if (idx == 0) { g_tw[0] = make_float2(1.0f, 0.0f); return; }
    int h = 1 << (31 - __clz(idx));
    int p = idx - h;
    float s, c;
    sincospif(-(float)p / (float)h, &s, &c);
    g_tw[idx] = make_float2(c, s);
}

// ---------------------------------------------------------------------------
// Stage 1: pack z = bf16(x) + i*h (rows n1>=32 are zero) + 64-pt FFT along n1
// (two register radix-8 passes, one smem exchange) + twiddle W_N^{k1*n2}.
// Output (fp16): g_zh[s][k1*2048 + n2]
// ---------------------------------------------------------------------------
__global__ void __launch_bounds__(256) k_stage1(const float* __restrict__ x,
                                                const float* __restrict__ hk) {
    __shared__ float2 sm[64 * 32];
    const int s   = blockIdx.y;
    const int col = threadIdx.x & 31;
    const int a   = threadIdx.x >> 5;          // 0..7
    const int n2  = blockIdx.x * 32 + col;
    const float* xs = x  + (size_t)s * T_LEN;
    const float* hs = hk + (size_t)s * T_LEN;

    float2 v[8];
    #pragma unroll
    for (int b = 0; b < 4; b++) {
        int n = (a + 8*b) * N2 + n2;           // < 65536 always
        v[b] = make_float2(__bfloat162float(__float2bfloat16_rn(xs[n])), hs[n]);
    }
    // fft8 over b with upper half zero (t = z, s = z)
    {
        const float C = 0.70710678118654752440f;
        float2 t0=v[0], t1=v[1], t2=v[2], t3=v[3];
        float2 s0=v[0];
        float2 s1=cmul(v[1], make_float2(C,-C));
        float2 s2=mulnI(v[2]);
        float2 s3=cmul(v[3], make_float2(-C,-C));
        float2 a0=cadd(t0,t2), a1=csub(t0,t2), a2=cadd(t1,t3), a3=mulnI(csub(t1,t3));
        float2 b0=cadd(s0,s2), b1=csub(s0,s2), b2=cadd(s1,s3), b3=mulnI(csub(s1,s3));
        v[0]=cadd(a0,a2); v[4]=csub(a0,a2);
        v[2]=cadd(a1,a3); v[6]=csub(a1,a3);
        v[1]=cadd(b0,b2); v[5]=csub(b0,b2);
        v[3]=cadd(b1,b3); v[7]=csub(b1,b3);
    }
    // twiddle W_64^{a*j}
    {
        float2 W[8];
        twpow(W, twid(32, a));
        #pragma unroll
        for (int j = 1; j < 8; j++) v[j] = cmul(v[j], W[j]);
    }
    #pragma unroll
    for (int j = 0; j < 8; j++) sm[(j*8 + a)*32 + col] = v[j];
    __syncthreads();

    const int j = a;                            // phase-2 role
    #pragma unroll
    for (int q = 0; q < 8; q++) v[q] = sm[(j*8 + q)*32 + col];
    fft8<false>(v);                             // over a -> m ; k1 = j + 8m

    __half2* zs = g_zh + (size_t)s * NN;
    {
        float2 acc  = twid(NHALF, n2 * j);      // n2*j < 65536
        float2 step = twid(NHALF, 8 * n2);
        #pragma unroll
        for (int m = 0; m < 8; m++) {
            int k1 = j + 8*m;
            float2 y = cmul(v[m], acc);
            zs[k1 * N2 + n2] = __floats2half2_rn(y.x, y.y);
            acc = cmul(acc, step);
        }
    }
}

// ---------------------------------------------------------------------------
// Stage 2 (radix-16 plan 2048 = 16x16x8, 256 threads, 3 blocks/SM):
// pair {g, 64-g} ({0,32} for g==0).
//   S1: radix-16 str 128 (2 rows x 128 groups = 256 threads)
//   S2: radix-16 str 8   (2 rows x 128 groups)
//   FUSED S3(fwd r8, contiguous blocks) + pointwise + IS3(inv r8), in regs:
//     A block u pairs with B block 255-u reversed (p <-> 2047-p identity).
//   IS2/IS1: radix-16 inverse, row A only (g==0: both rows), serial twiddle
//   chains interleaved with loads; IS1 applies conj inter-twiddle
//   W_N^{-row*n2} with 1/N folded, stores rows 0..32 fp16.
// ---------------------------------------------------------------------------
__global__ void __launch_bounds__(256, 3) k_stage2() {
    __shared__ float2 smA[2304];
    __shared__ float2 smB[2304];
    const int s = blockIdx.y;
    const int g = blockIdx.x;                   // 0..31
    const int rowA = g;
    const int rowB = (g == 0) ? 32 : 64 - g;
    const int u = threadIdx.x;                  // 0..255
    const __half2* zb = g_zh + (size_t)s * NN;

    float2 v[16];

    // ---- S1: radix-16 over stride 128, twiddle W_2048^{c*j} ----
    {
        const int r = u >> 7, c = u & 127;
        const __half2* glob = zb + (r ? rowB : rowA) * N2;
        float2* sm = r ? smB : smA;
        #pragma unroll
        for (int t = 0; t < 16; t++) v[t] = __half22float2(glob[c + 128*t]);
        fft16<false>(v);
        float2 w = twid(1024, c), acc = w;
        sm[PAD(c)] = v[0];
        #pragma unroll
        for (int j = 1; j < 16; j++) {
            sm[PAD(128*j + c)] = cmul(v[j], acc);
            acc = cmul(acc, w);
        }
    }
    __syncthreads();

    // ---- S2: radix-16 over stride 8, twiddle W_128^{e*j2} ----
    {
        const int r = u >> 7, idx = u & 127, j = idx >> 3, e = idx & 7;
        float2* sm = r ? smB : smA;
        const int base = 128*j + e;
        #pragma unroll
        for (int t2 = 0; t2 < 16; t2++) v[t2] = sm[PAD(base + 8*t2)];
        fft16<false>(v);
        float2 w = twid(64, e), acc = w;
        sm[PAD(base)] = v[0];
        #pragma unroll
        for (int j2 = 1; j2 < 16; j2++) {
            sm[PAD(128*j + 8*j2 + e)] = cmul(v[j2], acc);
            acc = cmul(acc, w);
        }
    }
    __syncthreads();

    if (g != 0) {
        // FUSED S3 fwd (A and B) + pointwise + IS3, all in registers.
        // A position p = 8u + j3 pairs with B position 2047-p = 8(255-u)+(7-j3).
        float2 a8[8], b8[8];
        #pragma unroll
        for (int e = 0; e < 8; e++) {
            a8[e] = smA[PAD(8*u + e)];
            b8[e] = smB[PAD(8*(255 - u) + e)];
        }
        fft8<false>(a8);
        fft8<false>(b8);
        float2 ya[8];
        #pragma unroll
        for (int j3 = 0; j3 < 8; j3++) ya[j3] = pw(a8[j3], b8[7 - j3]);
        fft8<true>(ya);
        #pragma unroll
        for (int e = 0; e < 8; e++) smA[PAD(8*u + e)] = ya[e];
    } else {
        // g==0: S3 forward both rows (in place per thread block-of-8)
        #pragma unroll
        for (int r = 0; r < 2; r++) {
            float2* sm = r ? smB : smA;
            float2 s8[8];
            #pragma unroll
            for (int e = 0; e < 8; e++) s8[e] = sm[PAD(8*u + e)];
            fft8<false>(s8);
            #pragma unroll
            for (int j3 = 0; j3 < 8; j3++) sm[PAD(8*u + j3)] = s8[j3];
        }
        __syncthreads();
        // row 0: pairs k2 <-> (2048-k2) mod 2048 (explicit POS16)
        #pragma unroll
        for (int e = 0; e < 4; e++) {
            int k2 = 4*u + e;                    // 0..1023
            int pa = POS16(k2);
            int pb = POS16((2048 - k2) & 2047);
            float2 Za = smA[PAD(pa)];
            float2 Zb = smA[PAD(pb)];
            float2 Y = pw(Za, Zb);
            smA[PAD(pa)] = Y;
            smA[PAD(pb)] = cconj(Y);
        }
        if (u == 0) {                            // k2 = 1024 self-pair
            int pa = POS16(1024);
            float2 Za = smA[PAD(pa)];
            smA[PAD(pa)] = pw(Za, Za);
        }
        // row 32: position-local p <-> 2047-p
        #pragma unroll
        for (int e = 0; e < 4; e++) {
            int p = 4*u + e;                     // 0..1023
            float2 Za = smB[PAD(p)];
            float2 Zb = smB[PAD(2047 - p)];
            float2 Y = pw(Za, Zb);
            smB[PAD(p)]        = Y;
            smB[PAD(2047 - p)] = cconj(Y);
        }
        __syncthreads();
        // IS3 both rows
        #pragma unroll
        for (int r = 0; r < 2; r++) {
            float2* sm = r ? smB : smA;
            float2 s8[8];
            #pragma unroll
            for (int j3 = 0; j3 < 8; j3++) s8[j3] = sm[PAD(8*u + j3)];
            fft8<true>(s8);
            #pragma unroll
            for (int e = 0; e < 8; e++) sm[PAD(8*u + e)] = s8[e];
        }
    }
    __syncthreads();

    const int rI = u >> 7, idxI = u & 127;
    const bool act = (rI == 0) || (g == 0);
    float2* smI = rI ? smB : smA;
    const int rowI = rI ? rowB : rowA;

    // ---- IS2: conj twiddle W_128^{-e*j2} (input side), inverse radix-16 ----
    // In-place safe: writes have low3 bits == e, only read by the same thread.
    if (act) {
        const int j = idxI >> 3, e = idxI & 7;
        float2 wc = twidc(64, e), acc = wc;
        v[0] = smI[PAD(128*j + e)];
        #pragma unroll
        for (int j2 = 1; j2 < 16; j2++) {
            v[j2] = cmul(smI[PAD(128*j + 8*j2 + e)], acc);
            acc = cmul(acc, wc);
        }
        fft16<true>(v);
        #pragma unroll
        for (int t2 = 0; t2 < 16; t2++) smI[PAD(128*j + e + 8*t2)] = v[t2];
    }
    __syncthreads();

    // ---- IS1: conj twiddle W_2048^{-c*j}, inverse radix-16, inter-twiddle
    //      W_N^{-row*(c+128t)} with 1/N folded, store fp16 ----
    if (act) {
        const int c = idxI;
        float2 wc = twidc(1024, c), acc = wc;
        v[0] = smI[PAD(c)];
        #pragma unroll
        for (int j = 1; j < 16; j++) {
            v[j] = cmul(smI[PAD(128*j + c)], acc);
            acc = cmul(acc, wc);
        }
        fft16<true>(v);
        const float SC = 1.0f / (float)NN;
        float2 a2 = twidc(NHALF, rowI * c);      // rowI*c <= 32*127 < 65536
        a2.x *= SC; a2.y *= SC;
        float2 st = twidc(NHALF, 128 * rowI);    // <= 4096
        __half2* gh = g_h + (size_t)s * (33 * N2) + rowI * N2;
        #pragma unroll
        for (int t = 0; t < 16; t++) {
            float2 y = cmul(v[t], a2);
            gh[c + 128*t] = __floats2half2_rn(y.x, y.y);
            a2 = cmul(a2, st);
        }
    }
}

// ---------------------------------------------------------------------------
// Stage 3 (real-output half-size IFFT): per column n2, build
//   G[k] = (U[k] + conj(U[32-k])) + i*w^k*(U[k] - conj(U[32-k])), w=e^{2pi i/64}
// from U rows 0..32 (fp16), then z = IFFT_32(G): y[2n]=Re z[n], y[2n+1]=Im z[n].
// We keep only y[0..31] (causal half) => store z[n] for n < 16 only.
// 32 = 8x4: 4 threads/col; thread m holds G[m+4t] -> fft8<inv> over t ->
// twiddle W_32^{n0*m} -> exchange -> fft4<inv> over m -> guarded stores.
// 1/N already folded in stage 2.
// ---------------------------------------------------------------------------
__global__ void __launch_bounds__(256) k_stage3(float* __restrict__ out) {
    __shared__ float2 sm[32 * 64];
    const int s   = blockIdx.y;
    const int col = threadIdx.x & 63;
    const int m   = threadIdx.x >> 6;            // 0..3
    const int n2  = blockIdx.x * 64 + col;
    const __half2* gh = g_h + (size_t)s * (33 * N2);

    float2 v[8];
    // Build G[m+4t], t=0..7
    #pragma unroll
    for (int t = 0; t < 8; t++) {
        int k = m + 4*t;                         // 0..31
        float2 Uk = __half22float2(gh[k * N2 + n2]);
        float2 Uc = __half22float2(gh[(32 - k) * N2 + n2]);
        Uc.y = -Uc.y;                            // conj(U[32-k])
        float2 sum  = cadd(Uk, Uc);
        float2 diff = csub(Uk, Uc);
        float2 wk = twidc(32, k);                // e^{+2pi i k/64}
        v[t] = cadd(sum, mulpI(cmul(wk, diff))); // sum + i*w^k*diff
    }
    fft8<true>(v);                               // over t -> n0 (natural order)
    // twiddle W_32^{n0*m}, W_32 = e^{+2pi i/32}
    { float2 W[8];
      twpow(W, twidc(16, m));
      #pragma unroll
      for (int n0 = 1; n0 < 8; n0++) v[n0] = cmul(v[n0], W[n0]);
    }
    #pragma unroll
    for (int n0 = 0; n0 < 8; n0++) sm[(n0*4 + m)*64 + col] = v[n0];
    __syncthreads();

    // fft4<inv> over m for n0 in {2q, 2q+1}; keep z[n] only for n < 16
    const int q = m;                             // 0..3
    float* os = out + (size_t)s * T_LEN;
    #pragma unroll
    for (int h2 = 0; h2 < 2; h2++) {
        const int n0 = 2*q + h2;                 // 0..7
        float2 w4[4];
        #pragma unroll
        for (int mm = 0; mm < 4; mm++) w4[mm] = sm[(n0*4 + mm)*64 + col];
        fft4<true>(w4);                          // over m -> s4 ; n = n0 + 8*s4
        #pragma unroll
        for (int s4 = 0; s4 < 2; s4++) {         // n < 16 => y rows < 32 only
            int n = n0 + 8*s4;                   // 0..15
            os[(2*n)     * N2 + n2] = w4[s4].x;  // y[2n]
            os[(2*n + 1) * N2 + n2] = w4[s4].y;  // y[2n+1]
        }
    }
}

extern "C" void kernel_launch(void* const* d_in, const int* in_sizes, int n_in,
                              void* d_out, int out_size) {
    const float* x = (const float*)d_in[0];
    const float* h = (const float*)d_in[1];
    float* out = (float*)d_out;

    k_init_tw<<<NN / 256, 256>>>();
    k_stage1<<<dim3(N2 / 32, SEQ), 256>>>(x, h);
    k_stage2<<<dim3(32, SEQ), 256>>>();
    k_stage3<<<dim3(N2 / 64, SEQ), 256>>>(out);
}